// round 1
// baseline (speedup 1.0000x reference)
#include <cuda_runtime.h>

// Problem constants
#define BATCH 4
#define NTOK  1024
#define FDIM  1024
#define HEADS 16
#define HD    64
#define SEQ   2048   // 2*NTOK

// ---------------------------------------------------------------------------
// Scratch (static device globals: allowed; runtime allocation is not)
// ---------------------------------------------------------------------------
__device__ float g_qf[BATCH * NTOK * FDIM];   // 16 MB  feature-row Q
__device__ float g_kf[BATCH * NTOK * FDIM];   // 16 MB  feature-row K
__device__ float g_vf[BATCH * NTOK * FDIM];   // 16 MB  feature-row V
__device__ float g_qs[BATCH * FDIM];          // scene Q (one row per batch)
__device__ float g_ks[BATCH * FDIM];          // scene K
__device__ float g_vs[BATCH * FDIM];          // scene V
__device__ float g_attn[BATCH * SEQ * FDIM];  // 32 MB  attention output
__device__ float g_R1[SEQ];                   // R1[q] = sum_{k<N} exp(rel[q,k])

// ---------------------------------------------------------------------------
// SGEMM (NT): C[M,Nc] = A[M,K] * W[Nc,K]^T + bias[Nc]
// Both operands row-major with K contiguous. 128x128x16 tiles, 8x8 frags.
// M, Nc multiples of 128; K multiple of 16.
// ---------------------------------------------------------------------------
__global__ __launch_bounds__(256) void gemm_nt_bias(
    const float* __restrict__ A, const float* __restrict__ W,
    const float* __restrict__ bias, float* __restrict__ C,
    int M, int Ncols, int K)
{
    __shared__ float As[16][132];
    __shared__ float Ws[16][132];

    const int tid = threadIdx.x;
    const int bm  = blockIdx.y * 128;
    const int bn  = blockIdx.x * 128;
    const int ty  = tid >> 4;        // 0..15 -> C rows ty*8..+7
    const int tx  = tid & 15;        // 0..15 -> C cols tx*8..+7
    const int lrow = tid >> 1;       // 0..127 tile row for loads
    const int lk   = (tid & 1) << 3; // 0 or 8

    const float* Ap = A + (size_t)(bm + lrow) * K + lk;
    const float* Wp = W + (size_t)(bn + lrow) * K + lk;

    float acc[8][8];
#pragma unroll
    for (int i = 0; i < 8; i++)
#pragma unroll
        for (int j = 0; j < 8; j++) acc[i][j] = 0.f;

    float4 a0 = *(const float4*)(Ap);
    float4 a1 = *(const float4*)(Ap + 4);
    float4 w0 = *(const float4*)(Wp);
    float4 w1 = *(const float4*)(Wp + 4);

    for (int k0 = 0; k0 < K; k0 += 16) {
        __syncthreads();
        As[lk + 0][lrow] = a0.x; As[lk + 1][lrow] = a0.y;
        As[lk + 2][lrow] = a0.z; As[lk + 3][lrow] = a0.w;
        As[lk + 4][lrow] = a1.x; As[lk + 5][lrow] = a1.y;
        As[lk + 6][lrow] = a1.z; As[lk + 7][lrow] = a1.w;
        Ws[lk + 0][lrow] = w0.x; Ws[lk + 1][lrow] = w0.y;
        Ws[lk + 2][lrow] = w0.z; Ws[lk + 3][lrow] = w0.w;
        Ws[lk + 4][lrow] = w1.x; Ws[lk + 5][lrow] = w1.y;
        Ws[lk + 6][lrow] = w1.z; Ws[lk + 7][lrow] = w1.w;
        __syncthreads();

        if (k0 + 16 < K) {  // prefetch next tile (overlaps compute)
            a0 = *(const float4*)(Ap + k0 + 16);
            a1 = *(const float4*)(Ap + k0 + 20);
            w0 = *(const float4*)(Wp + k0 + 16);
            w1 = *(const float4*)(Wp + k0 + 20);
        }

#pragma unroll
        for (int kk = 0; kk < 16; kk++) {
            float4 af0 = *(const float4*)&As[kk][ty * 8];
            float4 af1 = *(const float4*)&As[kk][ty * 8 + 4];
            float4 wf0 = *(const float4*)&Ws[kk][tx * 8];
            float4 wf1 = *(const float4*)&Ws[kk][tx * 8 + 4];
            float a[8] = {af0.x, af0.y, af0.z, af0.w, af1.x, af1.y, af1.z, af1.w};
            float w[8] = {wf0.x, wf0.y, wf0.z, wf0.w, wf1.x, wf1.y, wf1.z, wf1.w};
#pragma unroll
            for (int i = 0; i < 8; i++)
#pragma unroll
                for (int j = 0; j < 8; j++)
                    acc[i][j] = fmaf(a[i], w[j], acc[i][j]);
        }
    }

    float bv[8];
    const float* bp = bias + bn + tx * 8;
#pragma unroll
    for (int j = 0; j < 8; j++) bv[j] = bp[j];
#pragma unroll
    for (int i = 0; i < 8; i++) {
        float* Cp = C + (size_t)(bm + ty * 8 + i) * Ncols + bn + tx * 8;
        float4 r0 = make_float4(acc[i][0] + bv[0], acc[i][1] + bv[1],
                                acc[i][2] + bv[2], acc[i][3] + bv[3]);
        float4 r1 = make_float4(acc[i][4] + bv[4], acc[i][5] + bv[5],
                                acc[i][6] + bv[6], acc[i][7] + bv[7]);
        *(float4*)(Cp)     = r0;
        *(float4*)(Cp + 4) = r1;
    }
}

// ---------------------------------------------------------------------------
// Scene-token QKV: out[which][b,j] = scene[b,:] . W[j,:] + bias[j]
// 3 * 4 * 1024 = 12288 outputs, one warp each -> 1536 blocks of 256 threads
// ---------------------------------------------------------------------------
__global__ __launch_bounds__(256) void scene_qkv_kernel(
    const float* __restrict__ scene,
    const float* __restrict__ Wq, const float* __restrict__ bq,
    const float* __restrict__ Wk, const float* __restrict__ bk,
    const float* __restrict__ Wv, const float* __restrict__ bv,
    float* __restrict__ qs, float* __restrict__ ks, float* __restrict__ vs)
{
    int gw   = (blockIdx.x * 256 + threadIdx.x) >> 5;
    int lane = threadIdx.x & 31;
    int which = gw >> 12;     // 0,1,2
    int rem   = gw & 4095;
    int b = rem >> 10;
    int j = rem & 1023;

    const float* W; const float* bias; float* out;
    if (which == 0)      { W = Wq; bias = bq; out = qs; }
    else if (which == 1) { W = Wk; bias = bk; out = ks; }
    else                 { W = Wv; bias = bv; out = vs; }

    const float* x = scene + b * FDIM;
    const float* w = W + (size_t)j * FDIM;
    float acc = 0.f;
    for (int k = lane * 4; k < FDIM; k += 128) {
        float4 xv = *(const float4*)(x + k);
        float4 wv = *(const float4*)(w + k);
        acc = fmaf(xv.x, wv.x, acc);
        acc = fmaf(xv.y, wv.y, acc);
        acc = fmaf(xv.z, wv.z, acc);
        acc = fmaf(xv.w, wv.w, acc);
    }
#pragma unroll
    for (int o = 16; o; o >>= 1) acc += __shfl_xor_sync(0xffffffffu, acc, o);
    if (lane == 0) out[b * FDIM + j] = acc + bias[j];
}

// ---------------------------------------------------------------------------
// R1[q] = sum_{k<NTOK} exp(rel[q,k]); one warp per row (2048 rows)
// ---------------------------------------------------------------------------
__global__ __launch_bounds__(256) void r1_kernel(
    const float* __restrict__ rel, float* __restrict__ R1)
{
    int row  = (blockIdx.x * 256 + threadIdx.x) >> 5;
    int lane = threadIdx.x & 31;
    const float* r = rel + (size_t)row * SEQ;
    float acc = 0.f;
    for (int k = lane * 4; k < NTOK; k += 128) {
        float4 v = *(const float4*)(r + k);
        acc += __expf(v.x) + __expf(v.y) + __expf(v.z) + __expf(v.w);
    }
#pragma unroll
    for (int o = 16; o; o >>= 1) acc += __shfl_xor_sync(0xffffffffu, acc, o);
    if (lane == 0) R1[row] = acc;
}

// ---------------------------------------------------------------------------
// Attention, flash-style, exploiting scene-key factorization.
// Block = (b, h, 64 queries). Iterates 16 tiles of 64 feature keys.
// Scene-key block handled in closed form via R1.
// No max subtraction: |scores| <= ~7, all sums fp32-safe.
// Smem: Q[64][68] | K->P[64][68] | V[64][68] | ksc[64] | vsc[64]  ~52.7 KB
// ---------------------------------------------------------------------------
#define AST 68  // smem row stride (floats); 68*4=272 bytes, 16B aligned

__global__ __launch_bounds__(256) void attn_kernel(
    const float* __restrict__ rel,
    const float* __restrict__ qf, const float* __restrict__ kf,
    const float* __restrict__ vf,
    const float* __restrict__ qsb, const float* __restrict__ ksb,
    const float* __restrict__ vsb,
    const float* __restrict__ R1, float* __restrict__ attnO)
{
    extern __shared__ float sm[];
    float* Qs  = sm;
    float* KPs = sm + 64 * AST;       // K tile, then reused as P tile
    float* Vs  = sm + 2 * 64 * AST;
    float* ksc = sm + 3 * 64 * AST;
    float* vsc = ksc + 64;

    const int tid   = threadIdx.x;
    const int b     = blockIdx.z, h = blockIdx.y;
    const int qbase = blockIdx.x * 64;
    const int rowg  = tid >> 4;   // rows 4*rowg..+3
    const int colg  = tid & 15;   // S cols / O d-cols 4*colg..+3

    // Load Q tile (scene query rows are all identical)
    {
        int r  = tid >> 2;
        int d0 = (tid & 3) * 16;
        const float* src;
        if (qbase < NTOK)
            src = qsb + b * FDIM + h * HD + d0;
        else
            src = qf + (size_t)(b * NTOK + qbase - NTOK + r) * FDIM + h * HD + d0;
        float4* dst = (float4*)&Qs[r * AST + d0];
        const float4* s4 = (const float4*)src;
        dst[0] = s4[0]; dst[1] = s4[1]; dst[2] = s4[2]; dst[3] = s4[3];
    }
    if (tid < 64) {
        ksc[tid] = ksb[b * FDIM + h * HD + tid];
        vsc[tid] = vsb[b * FDIM + h * HD + tid];
    }
    __syncthreads();

    // Scene-key closed form: w0[i] = exp(q_r . k_scene / 8) * R1[q]
    float w0[4];
#pragma unroll
    for (int i = 0; i < 4; i++) {
        int r = rowg * 4 + i;
        float p = 0.f;
#pragma unroll
        for (int d = 0; d < 4; d++)
            p = fmaf(Qs[r * AST + colg * 4 + d], ksc[colg * 4 + d], p);
#pragma unroll
        for (int o = 8; o; o >>= 1) p += __shfl_xor_sync(0xffffffffu, p, o);
        w0[i] = __expf(p * 0.125f) * R1[qbase + r];
    }

    float oacc[4][4];
#pragma unroll
    for (int i = 0; i < 4; i++)
#pragma unroll
        for (int j = 0; j < 4; j++) oacc[i][j] = 0.f;
    float dpart[4] = {0.f, 0.f, 0.f, 0.f};

    for (int j0 = 0; j0 < NTOK; j0 += 64) {
        __syncthreads();  // prior PV reads of KPs/Vs complete
        {
            int kk = tid >> 2;
            int d0 = (tid & 3) * 16;
            const float4* ksrc = (const float4*)(kf + (size_t)(b * NTOK + j0 + kk) * FDIM + h * HD + d0);
            float4* kd = (float4*)&KPs[kk * AST + d0];
            kd[0] = ksrc[0]; kd[1] = ksrc[1]; kd[2] = ksrc[2]; kd[3] = ksrc[3];
            const float4* vsrc = (const float4*)(vf + (size_t)(b * NTOK + j0 + kk) * FDIM + h * HD + d0);
            float4* vd = (float4*)&Vs[kk * AST + d0];
            vd[0] = vsrc[0]; vd[1] = vsrc[1]; vd[2] = vsrc[2]; vd[3] = vsrc[3];
        }
        __syncthreads();

        // S = Q K^T  (4x4 frag per thread)
        float s[4][4];
#pragma unroll
        for (int i = 0; i < 4; i++)
#pragma unroll
            for (int j = 0; j < 4; j++) s[i][j] = 0.f;
#pragma unroll
        for (int d = 0; d < 64; d += 4) {
            float4 qv[4], kv[4];
#pragma unroll
            for (int i = 0; i < 4; i++) qv[i] = *(const float4*)&Qs[(rowg * 4 + i) * AST + d];
#pragma unroll
            for (int j = 0; j < 4; j++) kv[j] = *(const float4*)&KPs[(colg * 4 + j) * AST + d];
#pragma unroll
            for (int i = 0; i < 4; i++)
#pragma unroll
                for (int j = 0; j < 4; j++) {
                    s[i][j] = fmaf(qv[i].x, kv[j].x, s[i][j]);
                    s[i][j] = fmaf(qv[i].y, kv[j].y, s[i][j]);
                    s[i][j] = fmaf(qv[i].z, kv[j].z, s[i][j]);
                    s[i][j] = fmaf(qv[i].w, kv[j].w, s[i][j]);
                }
        }

        // bias + exp (no max subtraction needed, scores bounded)
#pragma unroll
        for (int i = 0; i < 4; i++) {
            const float4 rb = *(const float4*)(rel +
                (size_t)(qbase + rowg * 4 + i) * SEQ + NTOK + j0 + colg * 4);
            s[i][0] = __expf(fmaf(s[i][0], 0.125f, rb.x));
            s[i][1] = __expf(fmaf(s[i][1], 0.125f, rb.y));
            s[i][2] = __expf(fmaf(s[i][2], 0.125f, rb.z));
            s[i][3] = __expf(fmaf(s[i][3], 0.125f, rb.w));
            dpart[i] += s[i][0] + s[i][1] + s[i][2] + s[i][3];
        }

        __syncthreads();  // all K reads done; safe to overwrite with P
#pragma unroll
        for (int i = 0; i < 4; i++)
            *(float4*)&KPs[(rowg * 4 + i) * AST + colg * 4] =
                make_float4(s[i][0], s[i][1], s[i][2], s[i][3]);
        __syncthreads();

        // O += P V
#pragma unroll
        for (int c = 0; c < 64; c += 4) {
            float4 p4[4], v4[4];
#pragma unroll
            for (int i = 0; i < 4; i++) p4[i] = *(const float4*)&KPs[(rowg * 4 + i) * AST + c];
#pragma unroll
            for (int cc = 0; cc < 4; cc++) v4[cc] = *(const float4*)&Vs[(c + cc) * AST + colg * 4];
#pragma unroll
            for (int i = 0; i < 4; i++) {
                oacc[i][0] = fmaf(p4[i].x, v4[0].x, oacc[i][0]);
                oacc[i][0] = fmaf(p4[i].y, v4[1].x, oacc[i][0]);
                oacc[i][0] = fmaf(p4[i].z, v4[2].x, oacc[i][0]);
                oacc[i][0] = fmaf(p4[i].w, v4[3].x, oacc[i][0]);
                oacc[i][1] = fmaf(p4[i].x, v4[0].y, oacc[i][1]);
                oacc[i][1] = fmaf(p4[i].y, v4[1].y, oacc[i][1]);
                oacc[i][1] = fmaf(p4[i].z, v4[2].y, oacc[i][1]);
                oacc[i][1] = fmaf(p4[i].w, v4[3].y, oacc[i][1]);
                oacc[i][2] = fmaf(p4[i].x, v4[0].z, oacc[i][2]);
                oacc[i][2] = fmaf(p4[i].y, v4[1].z, oacc[i][2]);
                oacc[i][2] = fmaf(p4[i].z, v4[2].z, oacc[i][2]);
                oacc[i][2] = fmaf(p4[i].w, v4[3].z, oacc[i][2]);
                oacc[i][3] = fmaf(p4[i].x, v4[0].w, oacc[i][3]);
                oacc[i][3] = fmaf(p4[i].y, v4[1].w, oacc[i][3]);
                oacc[i][3] = fmaf(p4[i].z, v4[2].w, oacc[i][3]);
                oacc[i][3] = fmaf(p4[i].w, v4[3].w, oacc[i][3]);
            }
        }
    }

    // Finalize: denom = (col-partials reduced) + scene term; add scene V, divide
#pragma unroll
    for (int i = 0; i < 4; i++) {
        float den = dpart[i];
#pragma unroll
        for (int o = 8; o; o >>= 1) den += __shfl_xor_sync(0xffffffffu, den, o);
        den += w0[i];
        float inv = 1.0f / den;
        int r = qbase + rowg * 4 + i;
        float4 res;
        res.x = (oacc[i][0] + w0[i] * vsc[colg * 4 + 0]) * inv;
        res.y = (oacc[i][1] + w0[i] * vsc[colg * 4 + 1]) * inv;
        res.z = (oacc[i][2] + w0[i] * vsc[colg * 4 + 2]) * inv;
        res.w = (oacc[i][3] + w0[i] * vsc[colg * 4 + 3]) * inv;
        *(float4*)(attnO + (size_t)(b * SEQ + r) * FDIM + h * HD + colg * 4) = res;
    }
}

// ---------------------------------------------------------------------------
// Launch
// ---------------------------------------------------------------------------
extern "C" void kernel_launch(void* const* d_in, const int* in_sizes, int n_in,
                              void* d_out, int out_size)
{
    (void)in_sizes; (void)n_in; (void)out_size;
    const float* feature = (const float*)d_in[0];
    const float* scene   = (const float*)d_in[1];
    const float* rel     = (const float*)d_in[2];
    const float* Wq = (const float*)d_in[3];  const float* bq = (const float*)d_in[4];
    const float* Wk = (const float*)d_in[5];  const float* bk = (const float*)d_in[6];
    const float* Wv = (const float*)d_in[7];  const float* bv = (const float*)d_in[8];
    const float* Wo = (const float*)d_in[9];  const float* bo = (const float*)d_in[10];
    float* out = (float*)d_out;

    float *qf, *kf, *vf, *qs, *ks, *vs, *attn, *R1;
    cudaGetSymbolAddress((void**)&qf,   g_qf);
    cudaGetSymbolAddress((void**)&kf,   g_kf);
    cudaGetSymbolAddress((void**)&vf,   g_vf);
    cudaGetSymbolAddress((void**)&qs,   g_qs);
    cudaGetSymbolAddress((void**)&ks,   g_ks);
    cudaGetSymbolAddress((void**)&vs,   g_vs);
    cudaGetSymbolAddress((void**)&attn, g_attn);
    cudaGetSymbolAddress((void**)&R1,   g_R1);

    const int attn_smem = (3 * 64 * AST + 128) * (int)sizeof(float);  // 52736 B
    cudaFuncSetAttribute(attn_kernel,
                         cudaFuncAttributeMaxDynamicSharedMemorySize, attn_smem);

    // Scene-token QKV (tiny) + R1 (independent of QKV)
    scene_qkv_kernel<<<1536, 256>>>(scene, Wq, bq, Wk, bk, Wv, bv, qs, ks, vs);
    r1_kernel<<<256, 256>>>(rel, R1);

    // Feature-row QKV: [4096,1024] @ W^T
    dim3 gq(FDIM / 128, (BATCH * NTOK) / 128);  // (8, 32)
    gemm_nt_bias<<<gq, 256>>>(feature, Wq, bq, qf, BATCH * NTOK, FDIM, FDIM);
    gemm_nt_bias<<<gq, 256>>>(feature, Wk, bk, kf, BATCH * NTOK, FDIM, FDIM);
    gemm_nt_bias<<<gq, 256>>>(feature, Wv, bv, vf, BATCH * NTOK, FDIM, FDIM);

    // Attention: (qtile, head, batch)
    dim3 ga(SEQ / 64, HEADS, BATCH);  // (32, 16, 4)
    attn_kernel<<<ga, 256, attn_smem>>>(rel, qf, kf, vf, qs, ks, vs, R1, attn);

    // Output projection: [8192,1024] @ Wo^T + bo -> d_out
    dim3 go(FDIM / 128, (BATCH * SEQ) / 128);  // (8, 64)
    gemm_nt_bias<<<go, 256>>>(attn, Wo, bo, out, BATCH * SEQ, FDIM, FDIM);
}

// round 4
// speedup vs baseline: 1.3301x; 1.3301x over previous
#include <cuda_runtime.h>

// Problem constants
#define BATCH 4
#define NTOK  1024
#define FDIM  1024
#define HEADS 16
#define HD    64
#define SEQ   2048   // 2*NTOK

// ---------------------------------------------------------------------------
// Packed fp32x2 helpers (sm_103a FFMA2 — ptxas never auto-fuses; PTX only)
// ---------------------------------------------------------------------------
__device__ __forceinline__ unsigned long long dup2(float v) {
    unsigned long long r;
    asm("mov.b64 %0, {%1, %1};" : "=l"(r) : "f"(v));
    return r;
}
__device__ __forceinline__ void fma2(unsigned long long& d,
                                     unsigned long long a,
                                     unsigned long long b) {
    asm("fma.rn.f32x2 %0, %1, %2, %0;" : "+l"(d) : "l"(a), "l"(b));
}
__device__ __forceinline__ float2 up2(unsigned long long v) {
    float2 f;
    asm("mov.b64 {%0, %1}, %2;" : "=f"(f.x), "=f"(f.y) : "l"(v));
    return f;
}
union F4U { float4 f; unsigned long long u[2]; };

// ---------------------------------------------------------------------------
// Scratch
// ---------------------------------------------------------------------------
__device__ float g_qf[BATCH * NTOK * FDIM];
__device__ float g_kf[BATCH * NTOK * FDIM];
__device__ float g_vf[BATCH * NTOK * FDIM];
__device__ float g_qs[BATCH * FDIM];
__device__ float g_ks[BATCH * FDIM];
__device__ float g_vs[BATCH * FDIM];
__device__ float g_attn[BATCH * SEQ * FDIM];
__device__ float g_R1[SEQ];

// ---------------------------------------------------------------------------
// SGEMM (NT) with packed f32x2 inner product.
// C[M,Nc] = A[M,K] * W[Nc,K]^T + bias[Nc]. 128x128x16 tiles, 8x8 frags
// (accumulators packed in pairs along the column dim -> 8x4 ull).
// ---------------------------------------------------------------------------
__global__ __launch_bounds__(256) void gemm_nt_bias(
    const float* __restrict__ A, const float* __restrict__ W,
    const float* __restrict__ bias, float* __restrict__ C,
    int M, int Ncols, int K)
{
    __shared__ float As[16][132];
    __shared__ float Ws[16][132];

    const int tid = threadIdx.x;
    const int bm  = blockIdx.y * 128;
    const int bn  = blockIdx.x * 128;
    const int ty  = tid >> 4;
    const int tx  = tid & 15;
    const int lrow = tid >> 1;
    const int lk   = (tid & 1) << 3;

    const float* Ap = A + (size_t)(bm + lrow) * K + lk;
    const float* Wp = W + (size_t)(bn + lrow) * K + lk;

    unsigned long long acc2[8][4];
#pragma unroll
    for (int i = 0; i < 8; i++)
#pragma unroll
        for (int j = 0; j < 4; j++) acc2[i][j] = 0ull;  // (0.0f, 0.0f)

    float4 a0 = *(const float4*)(Ap);
    float4 a1 = *(const float4*)(Ap + 4);
    float4 w0 = *(const float4*)(Wp);
    float4 w1 = *(const float4*)(Wp + 4);

    for (int k0 = 0; k0 < K; k0 += 16) {
        __syncthreads();
        As[lk + 0][lrow] = a0.x; As[lk + 1][lrow] = a0.y;
        As[lk + 2][lrow] = a0.z; As[lk + 3][lrow] = a0.w;
        As[lk + 4][lrow] = a1.x; As[lk + 5][lrow] = a1.y;
        As[lk + 6][lrow] = a1.z; As[lk + 7][lrow] = a1.w;
        Ws[lk + 0][lrow] = w0.x; Ws[lk + 1][lrow] = w0.y;
        Ws[lk + 2][lrow] = w0.z; Ws[lk + 3][lrow] = w0.w;
        Ws[lk + 4][lrow] = w1.x; Ws[lk + 5][lrow] = w1.y;
        Ws[lk + 6][lrow] = w1.z; Ws[lk + 7][lrow] = w1.w;
        __syncthreads();

        if (k0 + 16 < K) {
            a0 = *(const float4*)(Ap + k0 + 16);
            a1 = *(const float4*)(Ap + k0 + 20);
            w0 = *(const float4*)(Wp + k0 + 16);
            w1 = *(const float4*)(Wp + k0 + 20);
        }

#pragma unroll
        for (int kk = 0; kk < 16; kk++) {
            F4U A0, A1, W0, W1;
            A0.f = *(const float4*)&As[kk][ty * 8];
            A1.f = *(const float4*)&As[kk][ty * 8 + 4];
            W0.f = *(const float4*)&Ws[kk][tx * 8];
            W1.f = *(const float4*)&Ws[kk][tx * 8 + 4];
            unsigned long long wp2[4] = {W0.u[0], W0.u[1], W1.u[0], W1.u[1]};
            float av[8] = {A0.f.x, A0.f.y, A0.f.z, A0.f.w,
                           A1.f.x, A1.f.y, A1.f.z, A1.f.w};
#pragma unroll
            for (int i = 0; i < 8; i++) {
                unsigned long long ai = dup2(av[i]);
#pragma unroll
                for (int j = 0; j < 4; j++) fma2(acc2[i][j], ai, wp2[j]);
            }
        }
    }

    float bv[8];
    const float* bp = bias + bn + tx * 8;
#pragma unroll
    for (int j = 0; j < 8; j++) bv[j] = bp[j];
#pragma unroll
    for (int i = 0; i < 8; i++) {
        float2 p0 = up2(acc2[i][0]);
        float2 p1 = up2(acc2[i][1]);
        float2 p2 = up2(acc2[i][2]);
        float2 p3 = up2(acc2[i][3]);
        float* Cp = C + (size_t)(bm + ty * 8 + i) * Ncols + bn + tx * 8;
        *(float4*)(Cp)     = make_float4(p0.x + bv[0], p0.y + bv[1],
                                         p1.x + bv[2], p1.y + bv[3]);
        *(float4*)(Cp + 4) = make_float4(p2.x + bv[4], p2.y + bv[5],
                                         p3.x + bv[6], p3.y + bv[7]);
    }
}

// ---------------------------------------------------------------------------
// Scene-token QKV: out[which][b,j] = scene[b,:] . W[j,:] + bias[j]
// ---------------------------------------------------------------------------
__global__ __launch_bounds__(256) void scene_qkv_kernel(
    const float* __restrict__ scene,
    const float* __restrict__ Wq, const float* __restrict__ bq,
    const float* __restrict__ Wk, const float* __restrict__ bk,
    const float* __restrict__ Wv, const float* __restrict__ bv,
    float* __restrict__ qs, float* __restrict__ ks, float* __restrict__ vs)
{
    int gw   = (blockIdx.x * 256 + threadIdx.x) >> 5;
    int lane = threadIdx.x & 31;
    int which = gw >> 12;
    int rem   = gw & 4095;
    int b = rem >> 10;
    int j = rem & 1023;

    const float* W; const float* bias; float* out;
    if (which == 0)      { W = Wq; bias = bq; out = qs; }
    else if (which == 1) { W = Wk; bias = bk; out = ks; }
    else                 { W = Wv; bias = bv; out = vs; }

    const float* x = scene + b * FDIM;
    const float* w = W + (size_t)j * FDIM;
    float acc = 0.f;
    for (int k = lane * 4; k < FDIM; k += 128) {
        float4 xv = *(const float4*)(x + k);
        float4 wv = *(const float4*)(w + k);
        acc = fmaf(xv.x, wv.x, acc);
        acc = fmaf(xv.y, wv.y, acc);
        acc = fmaf(xv.z, wv.z, acc);
        acc = fmaf(xv.w, wv.w, acc);
    }
#pragma unroll
    for (int o = 16; o; o >>= 1) acc += __shfl_xor_sync(0xffffffffu, acc, o);
    if (lane == 0) out[b * FDIM + j] = acc + bias[j];
}

// ---------------------------------------------------------------------------
// R1[q] = sum_{k<NTOK} exp(rel[q,k])
// ---------------------------------------------------------------------------
__global__ __launch_bounds__(256) void r1_kernel(
    const float* __restrict__ rel, float* __restrict__ R1)
{
    int row  = (blockIdx.x * 256 + threadIdx.x) >> 5;
    int lane = threadIdx.x & 31;
    const float* r = rel + (size_t)row * SEQ;
    float acc = 0.f;
    for (int k = lane * 4; k < NTOK; k += 128) {
        float4 v = *(const float4*)(r + k);
        acc += __expf(v.x) + __expf(v.y) + __expf(v.z) + __expf(v.w);
    }
#pragma unroll
    for (int o = 16; o; o >>= 1) acc += __shfl_xor_sync(0xffffffffu, acc, o);
    if (lane == 0) R1[row] = acc;
}

// ---------------------------------------------------------------------------
// Attention with f32x2 inner loops.
// K tile stored TRANSPOSED in smem (Kt[d][k]) so column pairs for FFMA2 come
// free from vector loads; same buffer reused afterwards for P[q][c].
// Smem: Q[64][68] | Kt/P[64][68] | V[64][68] | ksc[64] | vsc[64]  ~52.7 KB
// ---------------------------------------------------------------------------
#define AST 68

__global__ __launch_bounds__(256) void attn_kernel(
    const float* __restrict__ rel,
    const float* __restrict__ qf, const float* __restrict__ kf,
    const float* __restrict__ vf,
    const float* __restrict__ qsb, const float* __restrict__ ksb,
    const float* __restrict__ vsb,
    const float* __restrict__ R1, float* __restrict__ attnO)
{
    extern __shared__ float sm[];
    float* Qs  = sm;
    float* KPs = sm + 64 * AST;       // Kt tile, then reused as P tile
    float* Vs  = sm + 2 * 64 * AST;
    float* ksc = sm + 3 * 64 * AST;
    float* vsc = ksc + 64;

    const int tid   = threadIdx.x;
    const int b     = blockIdx.z, h = blockIdx.y;
    const int qbase = blockIdx.x * 64;
    const int rowg  = tid >> 4;
    const int colg  = tid & 15;

    // Load Q tile (scene query rows are all identical)
    {
        int r  = tid >> 2;
        int d0 = (tid & 3) * 16;
        const float* src;
        if (qbase < NTOK)
            src = qsb + b * FDIM + h * HD + d0;
        else
            src = qf + (size_t)(b * NTOK + qbase - NTOK + r) * FDIM + h * HD + d0;
        float4* dst = (float4*)&Qs[r * AST + d0];
        const float4* s4 = (const float4*)src;
        dst[0] = s4[0]; dst[1] = s4[1]; dst[2] = s4[2]; dst[3] = s4[3];
    }
    if (tid < 64) {
        ksc[tid] = ksb[b * FDIM + h * HD + tid];
        vsc[tid] = vsb[b * FDIM + h * HD + tid];
    }
    __syncthreads();

    // Scene-key closed form: w0[i] = exp(q_r . k_scene / 8) * R1[q]
    float w0[4];
#pragma unroll
    for (int i = 0; i < 4; i++) {
        int r = rowg * 4 + i;
        float p = 0.f;
#pragma unroll
        for (int d = 0; d < 4; d++)
            p = fmaf(Qs[r * AST + colg * 4 + d], ksc[colg * 4 + d], p);
#pragma unroll
        for (int o = 8; o; o >>= 1) p += __shfl_xor_sync(0xffffffffu, p, o);
        w0[i] = __expf(p * 0.125f) * R1[qbase + r];
    }

    unsigned long long o2[4][2];
#pragma unroll
    for (int i = 0; i < 4; i++) { o2[i][0] = 0ull; o2[i][1] = 0ull; }
    float dpart[4] = {0.f, 0.f, 0.f, 0.f};

    for (int j0 = 0; j0 < NTOK; j0 += 64) {
        __syncthreads();
        {
            int kk = tid >> 2;
            int d0 = (tid & 3) * 16;
            const float4* ksrc = (const float4*)(kf + (size_t)(b * NTOK + j0 + kk) * FDIM + h * HD + d0);
            float4 k0v = ksrc[0], k1v = ksrc[1], k2v = ksrc[2], k3v = ksrc[3];
            // transposed store: KPs[d][k]
            float* kt = KPs + kk;
            kt[(d0 +  0) * AST] = k0v.x; kt[(d0 +  1) * AST] = k0v.y;
            kt[(d0 +  2) * AST] = k0v.z; kt[(d0 +  3) * AST] = k0v.w;
            kt[(d0 +  4) * AST] = k1v.x; kt[(d0 +  5) * AST] = k1v.y;
            kt[(d0 +  6) * AST] = k1v.z; kt[(d0 +  7) * AST] = k1v.w;
            kt[(d0 +  8) * AST] = k2v.x; kt[(d0 +  9) * AST] = k2v.y;
            kt[(d0 + 10) * AST] = k2v.z; kt[(d0 + 11) * AST] = k2v.w;
            kt[(d0 + 12) * AST] = k3v.x; kt[(d0 + 13) * AST] = k3v.y;
            kt[(d0 + 14) * AST] = k3v.z; kt[(d0 + 15) * AST] = k3v.w;

            const float4* vsrc = (const float4*)(vf + (size_t)(b * NTOK + j0 + kk) * FDIM + h * HD + d0);
            float4* vd = (float4*)&Vs[kk * AST + d0];
            vd[0] = vsrc[0]; vd[1] = vsrc[1]; vd[2] = vsrc[2]; vd[3] = vsrc[3];
        }
        __syncthreads();

        // S = Q K^T  (packed pairs along the key dim)
        unsigned long long s2[4][2];
#pragma unroll
        for (int i = 0; i < 4; i++) { s2[i][0] = 0ull; s2[i][1] = 0ull; }
#pragma unroll
        for (int d = 0; d < 64; d += 4) {
            float4 qv[4];
#pragma unroll
            for (int i = 0; i < 4; i++) qv[i] = *(const float4*)&Qs[(rowg * 4 + i) * AST + d];
            F4U kt[4];
#pragma unroll
            for (int dd = 0; dd < 4; dd++) kt[dd].f = *(const float4*)&KPs[(d + dd) * AST + colg * 4];
#pragma unroll
            for (int i = 0; i < 4; i++) {
                unsigned long long t;
                t = dup2(qv[i].x); fma2(s2[i][0], t, kt[0].u[0]); fma2(s2[i][1], t, kt[0].u[1]);
                t = dup2(qv[i].y); fma2(s2[i][0], t, kt[1].u[0]); fma2(s2[i][1], t, kt[1].u[1]);
                t = dup2(qv[i].z); fma2(s2[i][0], t, kt[2].u[0]); fma2(s2[i][1], t, kt[2].u[1]);
                t = dup2(qv[i].w); fma2(s2[i][0], t, kt[3].u[0]); fma2(s2[i][1], t, kt[3].u[1]);
            }
        }

        // bias + exp (scores bounded; no max subtraction needed)
        float e[4][4];
#pragma unroll
        for (int i = 0; i < 4; i++) {
            float2 sa = up2(s2[i][0]);
            float2 sb = up2(s2[i][1]);
            const float4 rb = *(const float4*)(rel +
                (size_t)(qbase + rowg * 4 + i) * SEQ + NTOK + j0 + colg * 4);
            e[i][0] = __expf(fmaf(sa.x, 0.125f, rb.x));
            e[i][1] = __expf(fmaf(sa.y, 0.125f, rb.y));
            e[i][2] = __expf(fmaf(sb.x, 0.125f, rb.z));
            e[i][3] = __expf(fmaf(sb.y, 0.125f, rb.w));
            dpart[i] += e[i][0] + e[i][1] + e[i][2] + e[i][3];
        }

        __syncthreads();  // all Kt reads done; safe to overwrite with P
#pragma unroll
        for (int i = 0; i < 4; i++)
            *(float4*)&KPs[(rowg * 4 + i) * AST + colg * 4] =
                make_float4(e[i][0], e[i][1], e[i][2], e[i][3]);
        __syncthreads();

        // O += P V (packed pairs along output d)
#pragma unroll
        for (int c = 0; c < 64; c += 4) {
            float4 p4[4];
#pragma unroll
            for (int i = 0; i < 4; i++) p4[i] = *(const float4*)&KPs[(rowg * 4 + i) * AST + c];
            F4U v4[4];
#pragma unroll
            for (int cc = 0; cc < 4; cc++) v4[cc].f = *(const float4*)&Vs[(c + cc) * AST + colg * 4];
#pragma unroll
            for (int i = 0; i < 4; i++) {
                unsigned long long t;
                t = dup2(p4[i].x); fma2(o2[i][0], t, v4[0].u[0]); fma2(o2[i][1], t, v4[0].u[1]);
                t = dup2(p4[i].y); fma2(o2[i][0], t, v4[1].u[0]); fma2(o2[i][1], t, v4[1].u[1]);
                t = dup2(p4[i].z); fma2(o2[i][0], t, v4[2].u[0]); fma2(o2[i][1], t, v4[2].u[1]);
                t = dup2(p4[i].w); fma2(o2[i][0], t, v4[3].u[0]); fma2(o2[i][1], t, v4[3].u[1]);
            }
        }
    }

    // Finalize
#pragma unroll
    for (int i = 0; i < 4; i++) {
        float den = dpart[i];
#pragma unroll
        for (int o = 8; o; o >>= 1) den += __shfl_xor_sync(0xffffffffu, den, o);
        den += w0[i];
        float inv = 1.0f / den;
        int r = qbase + rowg * 4 + i;
        float2 oa = up2(o2[i][0]);
        float2 ob = up2(o2[i][1]);
        float4 res;
        res.x = (oa.x + w0[i] * vsc[colg * 4 + 0]) * inv;
        res.y = (oa.y + w0[i] * vsc[colg * 4 + 1]) * inv;
        res.z = (ob.x + w0[i] * vsc[colg * 4 + 2]) * inv;
        res.w = (ob.y + w0[i] * vsc[colg * 4 + 3]) * inv;
        *(float4*)(attnO + (size_t)(b * SEQ + r) * FDIM + h * HD + colg * 4) = res;
    }
}

// ---------------------------------------------------------------------------
// Launch
// ---------------------------------------------------------------------------
extern "C" void kernel_launch(void* const* d_in, const int* in_sizes, int n_in,
                              void* d_out, int out_size)
{
    (void)in_sizes; (void)n_in; (void)out_size;
    const float* feature = (const float*)d_in[0];
    const float* scene   = (const float*)d_in[1];
    const float* rel     = (const float*)d_in[2];
    const float* Wq = (const float*)d_in[3];  const float* bq = (const float*)d_in[4];
    const float* Wk = (const float*)d_in[5];  const float* bk = (const float*)d_in[6];
    const float* Wv = (const float*)d_in[7];  const float* bv = (const float*)d_in[8];
    const float* Wo = (const float*)d_in[9];  const float* bo = (const float*)d_in[10];
    float* out = (float*)d_out;

    float *qf, *kf, *vf, *qs, *ks, *vs, *attn, *R1;
    cudaGetSymbolAddress((void**)&qf,   g_qf);
    cudaGetSymbolAddress((void**)&kf,   g_kf);
    cudaGetSymbolAddress((void**)&vf,   g_vf);
    cudaGetSymbolAddress((void**)&qs,   g_qs);
    cudaGetSymbolAddress((void**)&ks,   g_ks);
    cudaGetSymbolAddress((void**)&vs,   g_vs);
    cudaGetSymbolAddress((void**)&attn, g_attn);
    cudaGetSymbolAddress((void**)&R1,   g_R1);

    const int attn_smem = (3 * 64 * AST + 128) * (int)sizeof(float);
    cudaFuncSetAttribute(attn_kernel,
                         cudaFuncAttributeMaxDynamicSharedMemorySize, attn_smem);

    scene_qkv_kernel<<<1536, 256>>>(scene, Wq, bq, Wk, bk, Wv, bv, qs, ks, vs);
    r1_kernel<<<256, 256>>>(rel, R1);

    dim3 gq(FDIM / 128, (BATCH * NTOK) / 128);
    gemm_nt_bias<<<gq, 256>>>(feature, Wq, bq, qf, BATCH * NTOK, FDIM, FDIM);
    gemm_nt_bias<<<gq, 256>>>(feature, Wk, bk, kf, BATCH * NTOK, FDIM, FDIM);
    gemm_nt_bias<<<gq, 256>>>(feature, Wv, bv, vf, BATCH * NTOK, FDIM, FDIM);

    dim3 ga(SEQ / 64, HEADS, BATCH);
    attn_kernel<<<ga, 256, attn_smem>>>(rel, qf, kf, vf, qs, ks, vs, R1, attn);

    dim3 go(FDIM / 128, (BATCH * SEQ) / 128);
    gemm_nt_bias<<<go, 256>>>(attn, Wo, bo, out, BATCH * SEQ, FDIM, FDIM);
}

// round 10
// speedup vs baseline: 1.7674x; 1.3288x over previous
#include <cuda_runtime.h>
#include <cuda_bf16.h>
#include <cstdint>

// Problem constants
#define BATCH 4
#define NTOK  1024
#define FDIM  1024
#define HEADS 16
#define HD    64
#define SEQ   2048   // 2*NTOK

// ===========================================================================
// Packed fp32x2 helpers (attention kernel)
// ===========================================================================
__device__ __forceinline__ unsigned long long dup2(float v) {
    unsigned long long r;
    asm("mov.b64 %0, {%1, %1};" : "=l"(r) : "f"(v));
    return r;
}
__device__ __forceinline__ void fma2(unsigned long long& d,
                                     unsigned long long a,
                                     unsigned long long b) {
    asm("fma.rn.f32x2 %0, %1, %2, %0;" : "+l"(d) : "l"(a), "l"(b));
}
__device__ __forceinline__ float2 up2(unsigned long long v) {
    float2 f;
    asm("mov.b64 {%0, %1}, %2;" : "=f"(f.x), "=f"(f.y) : "l"(v));
    return f;
}
union F4U { float4 f; unsigned long long u[2]; };

// ===========================================================================
// cp.async helpers (sm_80+ baseline PTX — no 'a' features)
// ===========================================================================
__device__ __forceinline__ uint32_t smem_u32(const void* p) {
    uint32_t a;
    asm("{ .reg .u64 t; cvta.to.shared.u64 t, %1; cvt.u32.u64 %0, t; }"
        : "=r"(a) : "l"(p));
    return a;
}
__device__ __forceinline__ void cp16(uint32_t dst, const void* src) {
    asm volatile("cp.async.ca.shared.global [%0], [%1], 16;" :: "r"(dst), "l"(src));
}
#define CP_COMMIT() asm volatile("cp.async.commit_group;" ::: "memory")
#define CP_WAIT(n)  asm volatile("cp.async.wait_group %0;" :: "n"(n) : "memory")

// bf16 tensor-core mma (HMMA): D = A(16x16) * B(16x8) + D, fp32 accum
__device__ __forceinline__ void mma_bf16(float* d, const uint32_t* a, const uint32_t* b) {
    asm volatile(
        "mma.sync.aligned.m16n8k16.row.col.f32.bf16.bf16.f32 "
        "{%0,%1,%2,%3}, {%4,%5,%6,%7}, {%8,%9}, {%0,%1,%2,%3};"
        : "+f"(d[0]), "+f"(d[1]), "+f"(d[2]), "+f"(d[3])
        : "r"(a[0]), "r"(a[1]), "r"(a[2]), "r"(a[3]), "r"(b[0]), "r"(b[1]));
}

// ===========================================================================
// Scratch
// ===========================================================================
__device__ float g_qf[BATCH * NTOK * FDIM];
__device__ float g_kf[BATCH * NTOK * FDIM];
__device__ float g_vf[BATCH * NTOK * FDIM];
__device__ float g_qs[BATCH * FDIM];
__device__ float g_ks[BATCH * FDIM];
__device__ float g_vs[BATCH * FDIM];
__device__ float g_attn[BATCH * SEQ * FDIM];
__device__ float g_R1[SEQ];
// bf16 hi/lo splits
__device__ __nv_bfloat16 g_fhi[BATCH * NTOK * FDIM];
__device__ __nv_bfloat16 g_flo[BATCH * NTOK * FDIM];
__device__ __nv_bfloat16 g_wqh[FDIM * FDIM];
__device__ __nv_bfloat16 g_wql[FDIM * FDIM];
__device__ __nv_bfloat16 g_wkh[FDIM * FDIM];
__device__ __nv_bfloat16 g_wkl[FDIM * FDIM];
__device__ __nv_bfloat16 g_wvh[FDIM * FDIM];
__device__ __nv_bfloat16 g_wvl[FDIM * FDIM];
__device__ __nv_bfloat16 g_woh[FDIM * FDIM];
__device__ __nv_bfloat16 g_wol[FDIM * FDIM];
__device__ __nv_bfloat16 g_ahi[BATCH * SEQ * FDIM];
__device__ __nv_bfloat16 g_alo[BATCH * SEQ * FDIM];

// ===========================================================================
// Split fp32 -> bf16 hi + bf16 lo (residual). n multiple of 4.
// ===========================================================================
__global__ __launch_bounds__(256) void split_kernel(
    const float* __restrict__ x, __nv_bfloat16* __restrict__ hi,
    __nv_bfloat16* __restrict__ lo, int n)
{
    int i = (blockIdx.x * 256 + threadIdx.x) * 4;
    if (i >= n) return;
    float4 v = *(const float4*)(x + i);
    __nv_bfloat16 h0 = __float2bfloat16(v.x);
    __nv_bfloat16 h1 = __float2bfloat16(v.y);
    __nv_bfloat16 h2 = __float2bfloat16(v.z);
    __nv_bfloat16 h3 = __float2bfloat16(v.w);
    __nv_bfloat16 l0 = __float2bfloat16(v.x - __bfloat162float(h0));
    __nv_bfloat16 l1 = __float2bfloat16(v.y - __bfloat162float(h1));
    __nv_bfloat16 l2 = __float2bfloat16(v.z - __bfloat162float(h2));
    __nv_bfloat16 l3 = __float2bfloat16(v.w - __bfloat162float(h3));
    *(__nv_bfloat162*)(hi + i)     = __nv_bfloat162(h0, h1);
    *(__nv_bfloat162*)(hi + i + 2) = __nv_bfloat162(h2, h3);
    *(__nv_bfloat162*)(lo + i)     = __nv_bfloat162(l0, l1);
    *(__nv_bfloat162*)(lo + i + 2) = __nv_bfloat162(l2, l3);
}

// ===========================================================================
// bf16x3 GEMM via mma.sync (NT): C[M,Nc] = (Ah+Al)(Bh+Bl)^T + bias
//   C = Ah Bh + Ah Bl + Al Bh  (fp32 accum)
// Block tile 128x128, 8 warps (2x4), warp tile 64x32.
// K-chunks of 32 bf16, cp.async double-buffered. KP=40 pad: conflict-free.
// ===========================================================================
#define GKC   32               // k per chunk (bf16)
#define NCH   (FDIM / GKC)     // 32 chunks
#define KP    40               // padded smem row (bf16 elems) -> 80 B
#define MAT_B (128 * KP * 2)   // 10240 B per matrix per buffer
#define BUF_B (4 * MAT_B)      // 40960 B per buffer (Ah, Al, Bh, Bl)
#define GSM_TOT (2 * BUF_B)    // 81920 B dynamic smem

__global__ __launch_bounds__(256) void gemm_mma(
    const __nv_bfloat16* __restrict__ Ah, const __nv_bfloat16* __restrict__ Al,
    const __nv_bfloat16* __restrict__ Bh, const __nv_bfloat16* __restrict__ Bl,
    const float* __restrict__ bias, float* __restrict__ C, int Ncols)
{
    extern __shared__ char smc[];
    const uint32_t smb = smem_u32(smc);
    const int tid  = threadIdx.x;
    const int wid  = tid >> 5;
    const int lane = tid & 31;
    const int wm = wid >> 2;          // 0..1 -> M offset wm*64
    const int wn = wid & 3;           // 0..3 -> N offset wn*32
    const int bm = blockIdx.y * 128;
    const int bn = blockIdx.x * 128;

    // Loader mapping: each thread owns half a row (32 B) per matrix
    const int lrow = tid >> 1;        // 0..127
    const int lhalf = tid & 1;        // 0/1 -> byte 0 / 32 within the 64B chunk row
    const __nv_bfloat16* gAh = Ah + (size_t)(bm + lrow) * FDIM + lhalf * 16;
    const __nv_bfloat16* gAl = Al + (size_t)(bm + lrow) * FDIM + lhalf * 16;
    const __nv_bfloat16* gBh = Bh + (size_t)(bn + lrow) * FDIM + lhalf * 16;
    const __nv_bfloat16* gBl = Bl + (size_t)(bn + lrow) * FDIM + lhalf * 16;
    const uint32_t soff = lrow * (KP * 2) + lhalf * 32;   // byte offset in matrix

    float acc[4][4][4];
#pragma unroll
    for (int mt = 0; mt < 4; mt++)
#pragma unroll
        for (int nt = 0; nt < 4; nt++)
#pragma unroll
            for (int k = 0; k < 4; k++) acc[mt][nt][k] = 0.f;

    // Issue chunk ck into buffer bsel
    auto issue = [&](int ck, int bsel) {
        const uint32_t base = smb + bsel * BUF_B + soff;
        const int ge = ck * GKC;      // element offset in gmem rows
        cp16(base + 0 * MAT_B,      gAh + ge);
        cp16(base + 0 * MAT_B + 16, gAh + ge + 8);
        cp16(base + 1 * MAT_B,      gAl + ge);
        cp16(base + 1 * MAT_B + 16, gAl + ge + 8);
        cp16(base + 2 * MAT_B,      gBh + ge);
        cp16(base + 2 * MAT_B + 16, gBh + ge + 8);
        cp16(base + 3 * MAT_B,      gBl + ge);
        cp16(base + 3 * MAT_B + 16, gBl + ge + 8);
    };

    issue(0, 0);
    CP_COMMIT();

    const int fr = lane >> 2;          // 0..7
    const int fc = (lane & 3) * 2;     // 0,2,4,6

    for (int c = 0; c < NCH; c++) {
        if (c + 1 < NCH) {
            issue(c + 1, (c + 1) & 1);
            CP_COMMIT();
            CP_WAIT(1);
        } else {
            CP_WAIT(0);
        }
        __syncthreads();

        const __nv_bfloat16* Ah_s = (const __nv_bfloat16*)(smc + (c & 1) * BUF_B + 0 * MAT_B);
        const __nv_bfloat16* Al_s = (const __nv_bfloat16*)(smc + (c & 1) * BUF_B + 1 * MAT_B);
        const __nv_bfloat16* Bh_s = (const __nv_bfloat16*)(smc + (c & 1) * BUF_B + 2 * MAT_B);
        const __nv_bfloat16* Bl_s = (const __nv_bfloat16*)(smc + (c & 1) * BUF_B + 3 * MAT_B);

#pragma unroll
        for (int ks = 0; ks < 2; ks++) {
            const int k0 = ks * 16 + fc;
            uint32_t ah[4][4], al[4][4], bh[4][2], bl[4][2];
#pragma unroll
            for (int mt = 0; mt < 4; mt++) {
                const int r = wm * 64 + mt * 16 + fr;
                ah[mt][0] = *(const uint32_t*)&Ah_s[r * KP + k0];
                ah[mt][1] = *(const uint32_t*)&Ah_s[(r + 8) * KP + k0];
                ah[mt][2] = *(const uint32_t*)&Ah_s[r * KP + k0 + 8];
                ah[mt][3] = *(const uint32_t*)&Ah_s[(r + 8) * KP + k0 + 8];
                al[mt][0] = *(const uint32_t*)&Al_s[r * KP + k0];
                al[mt][1] = *(const uint32_t*)&Al_s[(r + 8) * KP + k0];
                al[mt][2] = *(const uint32_t*)&Al_s[r * KP + k0 + 8];
                al[mt][3] = *(const uint32_t*)&Al_s[(r + 8) * KP + k0 + 8];
            }
#pragma unroll
            for (int nt = 0; nt < 4; nt++) {
                const int n = wn * 32 + nt * 8 + fr;
                bh[nt][0] = *(const uint32_t*)&Bh_s[n * KP + k0];
                bh[nt][1] = *(const uint32_t*)&Bh_s[n * KP + k0 + 8];
                bl[nt][0] = *(const uint32_t*)&Bl_s[n * KP + k0];
                bl[nt][1] = *(const uint32_t*)&Bl_s[n * KP + k0 + 8];
            }
#pragma unroll
            for (int mt = 0; mt < 4; mt++)
#pragma unroll
                for (int nt = 0; nt < 4; nt++) {
                    mma_bf16(acc[mt][nt], ah[mt], bh[nt]);
                    mma_bf16(acc[mt][nt], ah[mt], bl[nt]);
                    mma_bf16(acc[mt][nt], al[mt], bh[nt]);
                }
        }
        __syncthreads();
    }

    // Epilogue: direct STG (float2 pairs; 4 lanes x 8B = 32B sectors) + bias
#pragma unroll
    for (int nt = 0; nt < 4; nt++) {
        const int c0 = bn + wn * 32 + nt * 8 + (lane & 3) * 2;
        const float2 bv = *(const float2*)&bias[c0];
#pragma unroll
        for (int mt = 0; mt < 4; mt++) {
            const int r0 = bm + wm * 64 + mt * 16 + (lane >> 2);
            float2 v0 = make_float2(acc[mt][nt][0] + bv.x, acc[mt][nt][1] + bv.y);
            float2 v1 = make_float2(acc[mt][nt][2] + bv.x, acc[mt][nt][3] + bv.y);
            *(float2*)&C[(size_t)r0 * Ncols + c0]       = v0;
            *(float2*)&C[(size_t)(r0 + 8) * Ncols + c0] = v1;
        }
    }
}

// ===========================================================================
// Scene-token QKV (exact fp32)
// ===========================================================================
__global__ __launch_bounds__(256) void scene_qkv_kernel(
    const float* __restrict__ scene,
    const float* __restrict__ Wq, const float* __restrict__ bq,
    const float* __restrict__ Wk, const float* __restrict__ bk,
    const float* __restrict__ Wv, const float* __restrict__ bv,
    float* __restrict__ qs, float* __restrict__ ks, float* __restrict__ vs)
{
    int gw   = (blockIdx.x * 256 + threadIdx.x) >> 5;
    int lane = threadIdx.x & 31;
    int which = gw >> 12;
    int rem   = gw & 4095;
    int b = rem >> 10;
    int j = rem & 1023;

    const float* W; const float* bias; float* out;
    if (which == 0)      { W = Wq; bias = bq; out = qs; }
    else if (which == 1) { W = Wk; bias = bk; out = ks; }
    else                 { W = Wv; bias = bv; out = vs; }

    const float* x = scene + b * FDIM;
    const float* w = W + (size_t)j * FDIM;
    float acc = 0.f;
    for (int k = lane * 4; k < FDIM; k += 128) {
        float4 xv = *(const float4*)(x + k);
        float4 wv = *(const float4*)(w + k);
        acc = fmaf(xv.x, wv.x, acc);
        acc = fmaf(xv.y, wv.y, acc);
        acc = fmaf(xv.z, wv.z, acc);
        acc = fmaf(xv.w, wv.w, acc);
    }
#pragma unroll
    for (int o = 16; o; o >>= 1) acc += __shfl_xor_sync(0xffffffffu, acc, o);
    if (lane == 0) out[b * FDIM + j] = acc + bias[j];
}

// ===========================================================================
// R1[q] = sum_{k<NTOK} exp(rel[q,k])
// ===========================================================================
__global__ __launch_bounds__(256) void r1_kernel(
    const float* __restrict__ rel, float* __restrict__ R1)
{
    int row  = (blockIdx.x * 256 + threadIdx.x) >> 5;
    int lane = threadIdx.x & 31;
    const float* r = rel + (size_t)row * SEQ;
    float acc = 0.f;
    for (int k = lane * 4; k < NTOK; k += 128) {
        float4 v = *(const float4*)(r + k);
        acc += __expf(v.x) + __expf(v.y) + __expf(v.z) + __expf(v.w);
    }
#pragma unroll
    for (int o = 16; o; o >>= 1) acc += __shfl_xor_sync(0xffffffffu, acc, o);
    if (lane == 0) R1[row] = acc;
}

// ===========================================================================
// Attention (f32x2 scalar path — unchanged from the R3 passing version)
// ===========================================================================
#define AST 68

__global__ __launch_bounds__(256) void attn_kernel(
    const float* __restrict__ rel,
    const float* __restrict__ qf, const float* __restrict__ kf,
    const float* __restrict__ vf,
    const float* __restrict__ qsb, const float* __restrict__ ksb,
    const float* __restrict__ vsb,
    const float* __restrict__ R1, float* __restrict__ attnO)
{
    extern __shared__ float sm[];
    float* Qs  = sm;
    float* KPs = sm + 64 * AST;
    float* Vs  = sm + 2 * 64 * AST;
    float* ksc = sm + 3 * 64 * AST;
    float* vsc = ksc + 64;

    const int tid   = threadIdx.x;
    const int b     = blockIdx.z, h = blockIdx.y;
    const int qbase = blockIdx.x * 64;
    const int rowg  = tid >> 4;
    const int colg  = tid & 15;

    {
        int r  = tid >> 2;
        int d0 = (tid & 3) * 16;
        const float* src;
        if (qbase < NTOK)
            src = qsb + b * FDIM + h * HD + d0;
        else
            src = qf + (size_t)(b * NTOK + qbase - NTOK + r) * FDIM + h * HD + d0;
        float4* dst = (float4*)&Qs[r * AST + d0];
        const float4* s4 = (const float4*)src;
        dst[0] = s4[0]; dst[1] = s4[1]; dst[2] = s4[2]; dst[3] = s4[3];
    }
    if (tid < 64) {
        ksc[tid] = ksb[b * FDIM + h * HD + tid];
        vsc[tid] = vsb[b * FDIM + h * HD + tid];
    }
    __syncthreads();

    float w0[4];
#pragma unroll
    for (int i = 0; i < 4; i++) {
        int r = rowg * 4 + i;
        float p = 0.f;
#pragma unroll
        for (int d = 0; d < 4; d++)
            p = fmaf(Qs[r * AST + colg * 4 + d], ksc[colg * 4 + d], p);
#pragma unroll
        for (int o = 8; o; o >>= 1) p += __shfl_xor_sync(0xffffffffu, p, o);
        w0[i] = __expf(p * 0.125f) * R1[qbase + r];
    }

    unsigned long long o2[4][2];
#pragma unroll
    for (int i = 0; i < 4; i++) { o2[i][0] = 0ull; o2[i][1] = 0ull; }
    float dpart[4] = {0.f, 0.f, 0.f, 0.f};

    for (int j0 = 0; j0 < NTOK; j0 += 64) {
        __syncthreads();
        {
            int kk = tid >> 2;
            int d0 = (tid & 3) * 16;
            const float4* ksrc = (const float4*)(kf + (size_t)(b * NTOK + j0 + kk) * FDIM + h * HD + d0);
            float4 k0v = ksrc[0], k1v = ksrc[1], k2v = ksrc[2], k3v = ksrc[3];
            float* kt = KPs + kk;
            kt[(d0 +  0) * AST] = k0v.x; kt[(d0 +  1) * AST] = k0v.y;
            kt[(d0 +  2) * AST] = k0v.z; kt[(d0 +  3) * AST] = k0v.w;
            kt[(d0 +  4) * AST] = k1v.x; kt[(d0 +  5) * AST] = k1v.y;
            kt[(d0 +  6) * AST] = k1v.z; kt[(d0 +  7) * AST] = k1v.w;
            kt[(d0 +  8) * AST] = k2v.x; kt[(d0 +  9) * AST] = k2v.y;
            kt[(d0 + 10) * AST] = k2v.z; kt[(d0 + 11) * AST] = k2v.w;
            kt[(d0 + 12) * AST] = k3v.x; kt[(d0 + 13) * AST] = k3v.y;
            kt[(d0 + 14) * AST] = k3v.z; kt[(d0 + 15) * AST] = k3v.w;

            const float4* vsrc = (const float4*)(vf + (size_t)(b * NTOK + j0 + kk) * FDIM + h * HD + d0);
            float4* vd = (float4*)&Vs[kk * AST + d0];
            vd[0] = vsrc[0]; vd[1] = vsrc[1]; vd[2] = vsrc[2]; vd[3] = vsrc[3];
        }
        __syncthreads();

        unsigned long long s2[4][2];
#pragma unroll
        for (int i = 0; i < 4; i++) { s2[i][0] = 0ull; s2[i][1] = 0ull; }
#pragma unroll
        for (int d = 0; d < 64; d += 4) {
            float4 qv[4];
#pragma unroll
            for (int i = 0; i < 4; i++) qv[i] = *(const float4*)&Qs[(rowg * 4 + i) * AST + d];
            F4U kt[4];
#pragma unroll
            for (int dd = 0; dd < 4; dd++) kt[dd].f = *(const float4*)&KPs[(d + dd) * AST + colg * 4];
#pragma unroll
            for (int i = 0; i < 4; i++) {
                unsigned long long t;
                t = dup2(qv[i].x); fma2(s2[i][0], t, kt[0].u[0]); fma2(s2[i][1], t, kt[0].u[1]);
                t = dup2(qv[i].y); fma2(s2[i][0], t, kt[1].u[0]); fma2(s2[i][1], t, kt[1].u[1]);
                t = dup2(qv[i].z); fma2(s2[i][0], t, kt[2].u[0]); fma2(s2[i][1], t, kt[2].u[1]);
                t = dup2(qv[i].w); fma2(s2[i][0], t, kt[3].u[0]); fma2(s2[i][1], t, kt[3].u[1]);
            }
        }

        float e[4][4];
#pragma unroll
        for (int i = 0; i < 4; i++) {
            float2 sa = up2(s2[i][0]);
            float2 sb = up2(s2[i][1]);
            const float4 rb = *(const float4*)(rel +
                (size_t)(qbase + rowg * 4 + i) * SEQ + NTOK + j0 + colg * 4);
            e[i][0] = __expf(fmaf(sa.x, 0.125f, rb.x));
            e[i][1] = __expf(fmaf(sa.y, 0.125f, rb.y));
            e[i][2] = __expf(fmaf(sb.x, 0.125f, rb.z));
            e[i][3] = __expf(fmaf(sb.y, 0.125f, rb.w));
            dpart[i] += e[i][0] + e[i][1] + e[i][2] + e[i][3];
        }

        __syncthreads();
#pragma unroll
        for (int i = 0; i < 4; i++)
            *(float4*)&KPs[(rowg * 4 + i) * AST + colg * 4] =
                make_float4(e[i][0], e[i][1], e[i][2], e[i][3]);
        __syncthreads();

#pragma unroll
        for (int c = 0; c < 64; c += 4) {
            float4 p4[4];
#pragma unroll
            for (int i = 0; i < 4; i++) p4[i] = *(const float4*)&KPs[(rowg * 4 + i) * AST + c];
            F4U v4[4];
#pragma unroll
            for (int cc = 0; cc < 4; cc++) v4[cc].f = *(const float4*)&Vs[(c + cc) * AST + colg * 4];
#pragma unroll
            for (int i = 0; i < 4; i++) {
                unsigned long long t;
                t = dup2(p4[i].x); fma2(o2[i][0], t, v4[0].u[0]); fma2(o2[i][1], t, v4[0].u[1]);
                t = dup2(p4[i].y); fma2(o2[i][0], t, v4[1].u[0]); fma2(o2[i][1], t, v4[1].u[1]);
                t = dup2(p4[i].z); fma2(o2[i][0], t, v4[2].u[0]); fma2(o2[i][1], t, v4[2].u[1]);
                t = dup2(p4[i].w); fma2(o2[i][0], t, v4[3].u[0]); fma2(o2[i][1], t, v4[3].u[1]);
            }
        }
    }

#pragma unroll
    for (int i = 0; i < 4; i++) {
        float den = dpart[i];
#pragma unroll
        for (int o = 8; o; o >>= 1) den += __shfl_xor_sync(0xffffffffu, den, o);
        den += w0[i];
        float inv = 1.0f / den;
        int r = qbase + rowg * 4 + i;
        float2 oa = up2(o2[i][0]);
        float2 ob = up2(o2[i][1]);
        float4 res;
        res.x = (oa.x + w0[i] * vsc[colg * 4 + 0]) * inv;
        res.y = (oa.y + w0[i] * vsc[colg * 4 + 1]) * inv;
        res.z = (ob.x + w0[i] * vsc[colg * 4 + 2]) * inv;
        res.w = (ob.y + w0[i] * vsc[colg * 4 + 3]) * inv;
        *(float4*)(attnO + (size_t)(b * SEQ + r) * FDIM + h * HD + colg * 4) = res;
    }
}

// ===========================================================================
// Launch
// ===========================================================================
extern "C" void kernel_launch(void* const* d_in, const int* in_sizes, int n_in,
                              void* d_out, int out_size)
{
    (void)in_sizes; (void)n_in; (void)out_size;
    const float* feature = (const float*)d_in[0];
    const float* scene   = (const float*)d_in[1];
    const float* rel     = (const float*)d_in[2];
    const float* Wq = (const float*)d_in[3];  const float* bq = (const float*)d_in[4];
    const float* Wk = (const float*)d_in[5];  const float* bk = (const float*)d_in[6];
    const float* Wv = (const float*)d_in[7];  const float* bv = (const float*)d_in[8];
    const float* Wo = (const float*)d_in[9];  const float* bo = (const float*)d_in[10];
    float* out = (float*)d_out;

    float *qf, *kf, *vf, *qs, *ks, *vs, *attn, *R1;
    cudaGetSymbolAddress((void**)&qf,   g_qf);
    cudaGetSymbolAddress((void**)&kf,   g_kf);
    cudaGetSymbolAddress((void**)&vf,   g_vf);
    cudaGetSymbolAddress((void**)&qs,   g_qs);
    cudaGetSymbolAddress((void**)&ks,   g_ks);
    cudaGetSymbolAddress((void**)&vs,   g_vs);
    cudaGetSymbolAddress((void**)&attn, g_attn);
    cudaGetSymbolAddress((void**)&R1,   g_R1);

    __nv_bfloat16 *fhi, *flo, *wqh, *wql, *wkh, *wkl, *wvh, *wvl, *woh, *wol, *ahi, *alo;
    cudaGetSymbolAddress((void**)&fhi, g_fhi);
    cudaGetSymbolAddress((void**)&flo, g_flo);
    cudaGetSymbolAddress((void**)&wqh, g_wqh);
    cudaGetSymbolAddress((void**)&wql, g_wql);
    cudaGetSymbolAddress((void**)&wkh, g_wkh);
    cudaGetSymbolAddress((void**)&wkl, g_wkl);
    cudaGetSymbolAddress((void**)&wvh, g_wvh);
    cudaGetSymbolAddress((void**)&wvl, g_wvl);
    cudaGetSymbolAddress((void**)&woh, g_woh);
    cudaGetSymbolAddress((void**)&wol, g_wol);
    cudaGetSymbolAddress((void**)&ahi, g_ahi);
    cudaGetSymbolAddress((void**)&alo, g_alo);

    const int attn_smem = (3 * 64 * AST + 128) * (int)sizeof(float);
    cudaFuncSetAttribute(attn_kernel,
                         cudaFuncAttributeMaxDynamicSharedMemorySize, attn_smem);
    cudaFuncSetAttribute(gemm_mma,
                         cudaFuncAttributeMaxDynamicSharedMemorySize, GSM_TOT);

    const int NF = BATCH * NTOK * FDIM;   // 4,194,304
    const int NW = FDIM * FDIM;           // 1,048,576
    const int NA = BATCH * SEQ * FDIM;    // 8,388,608

    // Splits (feature + weights)
    split_kernel<<<NF / 1024, 256>>>(feature, fhi, flo, NF);
    split_kernel<<<NW / 1024, 256>>>(Wq, wqh, wql, NW);
    split_kernel<<<NW / 1024, 256>>>(Wk, wkh, wkl, NW);
    split_kernel<<<NW / 1024, 256>>>(Wv, wvh, wvl, NW);
    split_kernel<<<NW / 1024, 256>>>(Wo, woh, wol, NW);

    // Scene-token QKV (exact) + R1
    scene_qkv_kernel<<<1536, 256>>>(scene, Wq, bq, Wk, bk, Wv, bv, qs, ks, vs);
    r1_kernel<<<256, 256>>>(rel, R1);

    // Feature-row QKV via bf16x3 mma.sync: [4096,1024] @ W^T
    dim3 gq(FDIM / 128, (BATCH * NTOK) / 128);   // (8, 32)
    gemm_mma<<<gq, 256, GSM_TOT>>>(fhi, flo, wqh, wql, bq, qf, FDIM);
    gemm_mma<<<gq, 256, GSM_TOT>>>(fhi, flo, wkh, wkl, bk, kf, FDIM);
    gemm_mma<<<gq, 256, GSM_TOT>>>(fhi, flo, wvh, wvl, bv, vf, FDIM);

    // Attention
    dim3 ga(SEQ / 64, HEADS, BATCH);
    attn_kernel<<<ga, 256, attn_smem>>>(rel, qf, kf, vf, qs, ks, vs, R1, attn);

    // Output projection via bf16x3 mma.sync
    split_kernel<<<NA / 1024, 256>>>(attn, ahi, alo, NA);
    dim3 go(FDIM / 128, (BATCH * SEQ) / 128);    // (8, 64)
    gemm_mma<<<go, 256, GSM_TOT>>>(ahi, alo, woh, wol, bo, out, FDIM);
}

// round 12
// speedup vs baseline: 2.5351x; 1.4344x over previous
#include <cuda_runtime.h>
#include <cuda_bf16.h>
#include <cstdint>

// Problem constants
#define BATCH 4
#define NTOK  1024
#define FDIM  1024
#define HEADS 16
#define HD    64
#define SEQ   2048   // 2*NTOK

// ===========================================================================
// Helpers
// ===========================================================================
__device__ __forceinline__ uint32_t smem_u32(const void* p) {
    uint32_t a;
    asm("{ .reg .u64 t; cvta.to.shared.u64 t, %1; cvt.u32.u64 %0, t; }"
        : "=r"(a) : "l"(p));
    return a;
}
__device__ __forceinline__ void cp16(uint32_t dst, const void* src) {
    asm volatile("cp.async.ca.shared.global [%0], [%1], 16;" :: "r"(dst), "l"(src));
}
#define CP_COMMIT() asm volatile("cp.async.commit_group;" ::: "memory")
#define CP_WAIT(n)  asm volatile("cp.async.wait_group %0;" :: "n"(n) : "memory")

// bf16 tensor-core mma: D(16x8,f32) += A(16x16,bf16) * B(16x8,bf16)
__device__ __forceinline__ void mma_bf16(float* d, const uint32_t* a, const uint32_t* b) {
    asm volatile(
        "mma.sync.aligned.m16n8k16.row.col.f32.bf16.bf16.f32 "
        "{%0,%1,%2,%3}, {%4,%5,%6,%7}, {%8,%9}, {%0,%1,%2,%3};"
        : "+f"(d[0]), "+f"(d[1]), "+f"(d[2]), "+f"(d[3])
        : "r"(a[0]), "r"(a[1]), "r"(a[2]), "r"(a[3]), "r"(b[0]), "r"(b[1]));
}

// pack (x -> lower bf16, y -> upper bf16) hi + residual lo
__device__ __forceinline__ void pack_pair(float x, float y, uint32_t& hi, uint32_t& lo) {
    uint32_t h;
    asm("cvt.rn.bf16x2.f32 %0, %1, %2;" : "=r"(h) : "f"(y), "f"(x));
    float fx = __uint_as_float(h << 16);
    float fy = __uint_as_float(h & 0xFFFF0000u);
    uint32_t l;
    asm("cvt.rn.bf16x2.f32 %0, %1, %2;" : "=r"(l) : "f"(y - fy), "f"(x - fx));
    hi = h; lo = l;
}

// ===========================================================================
// Scratch
// ===========================================================================
__device__ float g_qf[BATCH * NTOK * FDIM];     // fp32 Q (for w0 kernel)
__device__ float g_qs[BATCH * FDIM];
__device__ float g_ks[BATCH * FDIM];
__device__ float g_vs[BATCH * FDIM];
__device__ float g_R1[SEQ];
__device__ float g_w0[BATCH * HEADS * SEQ];     // scene-key weights
// bf16 hi/lo splits
__device__ __nv_bfloat16 g_fhi[BATCH * NTOK * FDIM];
__device__ __nv_bfloat16 g_flo[BATCH * NTOK * FDIM];
__device__ __nv_bfloat16 g_wqh[FDIM * FDIM];
__device__ __nv_bfloat16 g_wql[FDIM * FDIM];
__device__ __nv_bfloat16 g_wkh[FDIM * FDIM];
__device__ __nv_bfloat16 g_wkl[FDIM * FDIM];
__device__ __nv_bfloat16 g_wvh[FDIM * FDIM];
__device__ __nv_bfloat16 g_wvl[FDIM * FDIM];
__device__ __nv_bfloat16 g_woh[FDIM * FDIM];
__device__ __nv_bfloat16 g_wol[FDIM * FDIM];
__device__ __nv_bfloat16 g_qhi[BATCH * NTOK * FDIM];
__device__ __nv_bfloat16 g_qlo[BATCH * NTOK * FDIM];
__device__ __nv_bfloat16 g_khi[BATCH * NTOK * FDIM];
__device__ __nv_bfloat16 g_klo[BATCH * NTOK * FDIM];
__device__ __nv_bfloat16 g_vhi[BATCH * NTOK * FDIM];
__device__ __nv_bfloat16 g_vlo[BATCH * NTOK * FDIM];
__device__ __nv_bfloat16 g_ahi[BATCH * SEQ * FDIM];
__device__ __nv_bfloat16 g_alo[BATCH * SEQ * FDIM];

// ===========================================================================
// Split fp32 -> bf16 hi + lo
// ===========================================================================
__global__ __launch_bounds__(256) void split_kernel(
    const float* __restrict__ x, __nv_bfloat16* __restrict__ hi,
    __nv_bfloat16* __restrict__ lo, int n)
{
    int i = (blockIdx.x * 256 + threadIdx.x) * 4;
    if (i >= n) return;
    float4 v = *(const float4*)(x + i);
    uint32_t h0, l0, h1, l1;
    pack_pair(v.x, v.y, h0, l0);
    pack_pair(v.z, v.w, h1, l1);
    *(uint32_t*)(hi + i)     = h0;
    *(uint32_t*)(hi + i + 2) = h1;
    *(uint32_t*)(lo + i)     = l0;
    *(uint32_t*)(lo + i + 2) = l1;
}

// ===========================================================================
// bf16x3 GEMM via mma.sync (NT): tile 128x128, 8 warps (2x4), warp 64x32.
// Optional fp32 C and/or bf16 hi/lo outputs.
// ===========================================================================
#define GKC   32
#define NCH   (FDIM / GKC)
#define KP    40
#define MAT_B (128 * KP * 2)
#define BUF_B (4 * MAT_B)
#define GSM_TOT (2 * BUF_B)

__global__ __launch_bounds__(256) void gemm_mma(
    const __nv_bfloat16* __restrict__ Ah, const __nv_bfloat16* __restrict__ Al,
    const __nv_bfloat16* __restrict__ Bh, const __nv_bfloat16* __restrict__ Bl,
    const float* __restrict__ bias, float* __restrict__ C,
    __nv_bfloat16* __restrict__ Chi, __nv_bfloat16* __restrict__ Clo, int Ncols)
{
    extern __shared__ char smc[];
    const uint32_t smb = smem_u32(smc);
    const int tid  = threadIdx.x;
    const int wid  = tid >> 5;
    const int lane = tid & 31;
    const int wm = wid >> 2;
    const int wn = wid & 3;
    const int bm = blockIdx.y * 128;
    const int bn = blockIdx.x * 128;

    const int lrow = tid >> 1;
    const int lhalf = tid & 1;
    const __nv_bfloat16* gAh = Ah + (size_t)(bm + lrow) * FDIM + lhalf * 16;
    const __nv_bfloat16* gAl = Al + (size_t)(bm + lrow) * FDIM + lhalf * 16;
    const __nv_bfloat16* gBh = Bh + (size_t)(bn + lrow) * FDIM + lhalf * 16;
    const __nv_bfloat16* gBl = Bl + (size_t)(bn + lrow) * FDIM + lhalf * 16;
    const uint32_t soff = lrow * (KP * 2) + lhalf * 32;

    float acc[4][4][4];
#pragma unroll
    for (int mt = 0; mt < 4; mt++)
#pragma unroll
        for (int nt = 0; nt < 4; nt++)
#pragma unroll
            for (int k = 0; k < 4; k++) acc[mt][nt][k] = 0.f;

    auto issue = [&](int ck, int bsel) {
        const uint32_t base = smb + bsel * BUF_B + soff;
        const int ge = ck * GKC;
        cp16(base + 0 * MAT_B,      gAh + ge);
        cp16(base + 0 * MAT_B + 16, gAh + ge + 8);
        cp16(base + 1 * MAT_B,      gAl + ge);
        cp16(base + 1 * MAT_B + 16, gAl + ge + 8);
        cp16(base + 2 * MAT_B,      gBh + ge);
        cp16(base + 2 * MAT_B + 16, gBh + ge + 8);
        cp16(base + 3 * MAT_B,      gBl + ge);
        cp16(base + 3 * MAT_B + 16, gBl + ge + 8);
    };

    issue(0, 0);
    CP_COMMIT();

    const int fr = lane >> 2;
    const int fc = (lane & 3) * 2;

    for (int c = 0; c < NCH; c++) {
        if (c + 1 < NCH) {
            issue(c + 1, (c + 1) & 1);
            CP_COMMIT();
            CP_WAIT(1);
        } else {
            CP_WAIT(0);
        }
        __syncthreads();

        const __nv_bfloat16* Ah_s = (const __nv_bfloat16*)(smc + (c & 1) * BUF_B + 0 * MAT_B);
        const __nv_bfloat16* Al_s = (const __nv_bfloat16*)(smc + (c & 1) * BUF_B + 1 * MAT_B);
        const __nv_bfloat16* Bh_s = (const __nv_bfloat16*)(smc + (c & 1) * BUF_B + 2 * MAT_B);
        const __nv_bfloat16* Bl_s = (const __nv_bfloat16*)(smc + (c & 1) * BUF_B + 3 * MAT_B);

#pragma unroll
        for (int ks = 0; ks < 2; ks++) {
            const int k0 = ks * 16 + fc;
            uint32_t ah[4][4], al[4][4], bh[4][2], bl[4][2];
#pragma unroll
            for (int mt = 0; mt < 4; mt++) {
                const int r = wm * 64 + mt * 16 + fr;
                ah[mt][0] = *(const uint32_t*)&Ah_s[r * KP + k0];
                ah[mt][1] = *(const uint32_t*)&Ah_s[(r + 8) * KP + k0];
                ah[mt][2] = *(const uint32_t*)&Ah_s[r * KP + k0 + 8];
                ah[mt][3] = *(const uint32_t*)&Ah_s[(r + 8) * KP + k0 + 8];
                al[mt][0] = *(const uint32_t*)&Al_s[r * KP + k0];
                al[mt][1] = *(const uint32_t*)&Al_s[(r + 8) * KP + k0];
                al[mt][2] = *(const uint32_t*)&Al_s[r * KP + k0 + 8];
                al[mt][3] = *(const uint32_t*)&Al_s[(r + 8) * KP + k0 + 8];
            }
#pragma unroll
            for (int nt = 0; nt < 4; nt++) {
                const int n = wn * 32 + nt * 8 + fr;
                bh[nt][0] = *(const uint32_t*)&Bh_s[n * KP + k0];
                bh[nt][1] = *(const uint32_t*)&Bh_s[n * KP + k0 + 8];
                bl[nt][0] = *(const uint32_t*)&Bl_s[n * KP + k0];
                bl[nt][1] = *(const uint32_t*)&Bl_s[n * KP + k0 + 8];
            }
#pragma unroll
            for (int mt = 0; mt < 4; mt++)
#pragma unroll
                for (int nt = 0; nt < 4; nt++) {
                    mma_bf16(acc[mt][nt], ah[mt], bh[nt]);
                    mma_bf16(acc[mt][nt], ah[mt], bl[nt]);
                    mma_bf16(acc[mt][nt], al[mt], bh[nt]);
                }
        }
        __syncthreads();
    }

#pragma unroll
    for (int nt = 0; nt < 4; nt++) {
        const int c0 = bn + wn * 32 + nt * 8 + (lane & 3) * 2;
        const float2 bv = *(const float2*)&bias[c0];
#pragma unroll
        for (int mt = 0; mt < 4; mt++) {
            const int r0 = bm + wm * 64 + mt * 16 + (lane >> 2);
            float2 v0 = make_float2(acc[mt][nt][0] + bv.x, acc[mt][nt][1] + bv.y);
            float2 v1 = make_float2(acc[mt][nt][2] + bv.x, acc[mt][nt][3] + bv.y);
            if (C) {
                *(float2*)&C[(size_t)r0 * Ncols + c0]       = v0;
                *(float2*)&C[(size_t)(r0 + 8) * Ncols + c0] = v1;
            }
            if (Chi) {
                uint32_t h0, l0, h1, l1;
                pack_pair(v0.x, v0.y, h0, l0);
                pack_pair(v1.x, v1.y, h1, l1);
                *(uint32_t*)&Chi[(size_t)r0 * Ncols + c0]       = h0;
                *(uint32_t*)&Clo[(size_t)r0 * Ncols + c0]       = l0;
                *(uint32_t*)&Chi[(size_t)(r0 + 8) * Ncols + c0] = h1;
                *(uint32_t*)&Clo[(size_t)(r0 + 8) * Ncols + c0] = l1;
            }
        }
    }
}

// ===========================================================================
// Scene-token QKV (exact fp32)
// ===========================================================================
__global__ __launch_bounds__(256) void scene_qkv_kernel(
    const float* __restrict__ scene,
    const float* __restrict__ Wq, const float* __restrict__ bq,
    const float* __restrict__ Wk, const float* __restrict__ bk,
    const float* __restrict__ Wv, const float* __restrict__ bv,
    float* __restrict__ qs, float* __restrict__ ks, float* __restrict__ vs)
{
    int gw   = (blockIdx.x * 256 + threadIdx.x) >> 5;
    int lane = threadIdx.x & 31;
    int which = gw >> 12;
    int rem   = gw & 4095;
    int b = rem >> 10;
    int j = rem & 1023;

    const float* W; const float* bias; float* out;
    if (which == 0)      { W = Wq; bias = bq; out = qs; }
    else if (which == 1) { W = Wk; bias = bk; out = ks; }
    else                 { W = Wv; bias = bv; out = vs; }

    const float* x = scene + b * FDIM;
    const float* w = W + (size_t)j * FDIM;
    float acc = 0.f;
    for (int k = lane * 4; k < FDIM; k += 128) {
        float4 xv = *(const float4*)(x + k);
        float4 wv = *(const float4*)(w + k);
        acc = fmaf(xv.x, wv.x, acc);
        acc = fmaf(xv.y, wv.y, acc);
        acc = fmaf(xv.z, wv.z, acc);
        acc = fmaf(xv.w, wv.w, acc);
    }
#pragma unroll
    for (int o = 16; o; o >>= 1) acc += __shfl_xor_sync(0xffffffffu, acc, o);
    if (lane == 0) out[b * FDIM + j] = acc + bias[j];
}

// ===========================================================================
// R1[q] = sum_{k<NTOK} exp(rel[q,k])
// ===========================================================================
__global__ __launch_bounds__(256) void r1_kernel(
    const float* __restrict__ rel, float* __restrict__ R1)
{
    int row  = (blockIdx.x * 256 + threadIdx.x) >> 5;
    int lane = threadIdx.x & 31;
    const float* r = rel + (size_t)row * SEQ;
    float acc = 0.f;
    for (int k = lane * 4; k < NTOK; k += 128) {
        float4 v = *(const float4*)(r + k);
        acc += __expf(v.x) + __expf(v.y) + __expf(v.z) + __expf(v.w);
    }
#pragma unroll
    for (int o = 16; o; o >>= 1) acc += __shfl_xor_sync(0xffffffffu, acc, o);
    if (lane == 0) R1[row] = acc;
}

// ===========================================================================
// w0[b,h,q] = exp(q_vec . k_scene / 8) * R1[q]   (one warp per q)
// ===========================================================================
__global__ __launch_bounds__(256) void w0_kernel(
    const float* __restrict__ qf, const float* __restrict__ qs,
    const float* __restrict__ ks, const float* __restrict__ R1,
    float* __restrict__ w0g)
{
    int gw   = (blockIdx.x * 256 + threadIdx.x) >> 5;  // 0..131071
    int lane = threadIdx.x & 31;
    int q  = gw & (SEQ - 1);
    int bh = gw >> 11;
    int b  = bh >> 4;
    int h  = bh & 15;
    const float* qv = (q < NTOK) ? qs + b * FDIM + h * HD
                                 : qf + (size_t)(b * NTOK + q - NTOK) * FDIM + h * HD;
    const float* kv = ks + b * FDIM + h * HD;
    float2 a = *(const float2*)(qv + lane * 2);
    float2 c = *(const float2*)(kv + lane * 2);
    float p = a.x * c.x + a.y * c.y;
#pragma unroll
    for (int o = 16; o; o >>= 1) p += __shfl_xor_sync(0xffffffffu, p, o);
    if (lane == 0) w0g[bh * SEQ + q] = __expf(p * 0.125f) * R1[q];
}

// ===========================================================================
// Flash attention via bf16x3 mma.sync.
// Block: 128 q rows of one (b,h). 8 warps x 16 q. 8 key-tiles of 128.
// smem: Kh/Kl [128][72] + Vth/Vtl [64][136]  (71680 B)
// ===========================================================================
#define BQ  128
#define BK  128
#define KSP 72
#define VSP 136
#define ASM_TOT ((2 * 128 * KSP + 2 * 64 * VSP) * 2)   // 71680

__global__ __launch_bounds__(256) void attn_mma(
    const __nv_bfloat16* __restrict__ qhi, const __nv_bfloat16* __restrict__ qlo,
    const __nv_bfloat16* __restrict__ khi, const __nv_bfloat16* __restrict__ klo,
    const __nv_bfloat16* __restrict__ vhi, const __nv_bfloat16* __restrict__ vlo,
    const float* __restrict__ qs, const float* __restrict__ vs_scene,
    const float* __restrict__ rel, const float* __restrict__ w0g,
    __nv_bfloat16* __restrict__ ahi, __nv_bfloat16* __restrict__ alo)
{
    extern __shared__ __nv_bfloat16 sb[];
    __nv_bfloat16* Kh  = sb;
    __nv_bfloat16* Kl  = sb + 128 * KSP;
    __nv_bfloat16* Vth = sb + 2 * 128 * KSP;
    __nv_bfloat16* Vtl = Vth + 64 * VSP;
    const uint32_t smb = smem_u32(sb);

    const int tid  = threadIdx.x;
    const int lane = tid & 31;
    const int wid  = tid >> 5;
    const int b  = blockIdx.z, h = blockIdx.y;
    const int q0 = blockIdx.x * BQ;
    const int fr = lane >> 2;
    const int c2 = (lane & 3) * 2;
    const int wq = wid * 16;

    // ---- stage Q into Kh/Kl, extract frags ----
    {
        int r = tid >> 1, half = tid & 1;
        int dbase = half * 32;
        if (q0 < NTOK) {
            const float* src = qs + b * FDIM + h * HD + dbase;
#pragma unroll
            for (int j = 0; j < 16; j++) {   // 16 float2 -> 32 d
                float2 v = *(const float2*)(src + j * 2);
                uint32_t hh, ll;
                pack_pair(v.x, v.y, hh, ll);
                *(uint32_t*)&Kh[r * KSP + dbase + j * 2] = hh;
                *(uint32_t*)&Kl[r * KSP + dbase + j * 2] = ll;
            }
        } else {
            const __nv_bfloat16* sh = qhi + (size_t)(b * NTOK + q0 - NTOK + r) * FDIM + h * HD + dbase;
            const __nv_bfloat16* sl = qlo + (size_t)(b * NTOK + q0 - NTOK + r) * FDIM + h * HD + dbase;
#pragma unroll
            for (int j = 0; j < 4; j++) {
                *(uint4*)&Kh[r * KSP + dbase + j * 8] = *(const uint4*)(sh + j * 8);
                *(uint4*)&Kl[r * KSP + dbase + j * 8] = *(const uint4*)(sl + j * 8);
            }
        }
    }
    __syncthreads();

    uint32_t qh[4][4], ql[4][4];
#pragma unroll
    for (int ks = 0; ks < 4; ks++) {
        int k0 = ks * 16 + c2;
        qh[ks][0] = *(const uint32_t*)&Kh[(wq + fr) * KSP + k0];
        qh[ks][1] = *(const uint32_t*)&Kh[(wq + fr + 8) * KSP + k0];
        qh[ks][2] = *(const uint32_t*)&Kh[(wq + fr) * KSP + k0 + 8];
        qh[ks][3] = *(const uint32_t*)&Kh[(wq + fr + 8) * KSP + k0 + 8];
        ql[ks][0] = *(const uint32_t*)&Kl[(wq + fr) * KSP + k0];
        ql[ks][1] = *(const uint32_t*)&Kl[(wq + fr + 8) * KSP + k0];
        ql[ks][2] = *(const uint32_t*)&Kl[(wq + fr) * KSP + k0 + 8];
        ql[ks][3] = *(const uint32_t*)&Kl[(wq + fr + 8) * KSP + k0 + 8];
    }

    float oacc[8][4];
#pragma unroll
    for (int nt = 0; nt < 8; nt++)
#pragma unroll
        for (int k = 0; k < 4; k++) oacc[nt][k] = 0.f;
    float den0 = 0.f, den1 = 0.f;

    const float* relp = rel + (size_t)(q0 + wq + fr) * SEQ + NTOK;

    for (int jt = 0; jt < 8; jt++) {
        __syncthreads();   // prior tile's K/Vt reads complete
        // K tiles via cp.async
        {
            int r = tid >> 1, half = tid & 1;
            int dbase = half * 32;
            const __nv_bfloat16* gkh = khi + (size_t)(b * NTOK + jt * BK + r) * FDIM + h * HD + dbase;
            const __nv_bfloat16* gkl = klo + (size_t)(b * NTOK + jt * BK + r) * FDIM + h * HD + dbase;
            uint32_t dh = smb + (r * KSP + dbase) * 2;
            uint32_t dl = smb + (128 * KSP + r * KSP + dbase) * 2;
#pragma unroll
            for (int j = 0; j < 4; j++) {
                cp16(dh + j * 16, gkh + j * 8);
                cp16(dl + j * 16, gkl + j * 8);
            }
        }
        CP_COMMIT();
        // V tiles: LDG + transposed STS
        {
            int key = tid & 127;
            int dg  = (tid >> 7) * 32;
            const uint4* gvh = (const uint4*)(vhi + (size_t)(b * NTOK + jt * BK + key) * FDIM + h * HD + dg);
            const uint4* gvl = (const uint4*)(vlo + (size_t)(b * NTOK + jt * BK + key) * FDIM + h * HD + dg);
#pragma unroll
            for (int j = 0; j < 4; j++) {
                uint4 uh = gvh[j];
                uint4 ul = gvl[j];
                const __nv_bfloat16* eh = (const __nv_bfloat16*)&uh;
                const __nv_bfloat16* el = (const __nv_bfloat16*)&ul;
#pragma unroll
                for (int t = 0; t < 8; t++) {
                    Vth[(dg + j * 8 + t) * VSP + key] = eh[t];
                    Vtl[(dg + j * 8 + t) * VSP + key] = el[t];
                }
            }
        }
        CP_WAIT(0);
        __syncthreads();

        // ---- S = QK^T (bf16x3) + bias + exp ----
        float sacc[16][4];
#pragma unroll
        for (int nt = 0; nt < 16; nt++) {
#pragma unroll
            for (int k = 0; k < 4; k++) sacc[nt][k] = 0.f;
#pragma unroll
            for (int ks = 0; ks < 4; ks++) {
                int k0 = ks * 16 + c2;
                uint32_t bhf[2], blf[2];
                bhf[0] = *(const uint32_t*)&Kh[(nt * 8 + fr) * KSP + k0];
                bhf[1] = *(const uint32_t*)&Kh[(nt * 8 + fr) * KSP + k0 + 8];
                blf[0] = *(const uint32_t*)&Kl[(nt * 8 + fr) * KSP + k0];
                blf[1] = *(const uint32_t*)&Kl[(nt * 8 + fr) * KSP + k0 + 8];
                mma_bf16(sacc[nt], qh[ks], bhf);
                mma_bf16(sacc[nt], qh[ks], blf);
                mma_bf16(sacc[nt], ql[ks], bhf);
            }
            // bias + exp
            int col = jt * BK + nt * 8 + c2;
            float2 rb0 = *(const float2*)(relp + col);
            float2 rb1 = *(const float2*)(relp + 8 * SEQ + col);
            sacc[nt][0] = __expf(fmaf(sacc[nt][0], 0.125f, rb0.x));
            sacc[nt][1] = __expf(fmaf(sacc[nt][1], 0.125f, rb0.y));
            sacc[nt][2] = __expf(fmaf(sacc[nt][2], 0.125f, rb1.x));
            sacc[nt][3] = __expf(fmaf(sacc[nt][3], 0.125f, rb1.y));
            den0 += sacc[nt][0] + sacc[nt][1];
            den1 += sacc[nt][2] + sacc[nt][3];
        }

        // ---- O += P V (bf16x3) ----
#pragma unroll
        for (int ks2 = 0; ks2 < 8; ks2++) {
            const float* e0 = sacc[2 * ks2];
            const float* e1 = sacc[2 * ks2 + 1];
            uint32_t pa_h[4], pa_l[4];
            pack_pair(e0[0], e0[1], pa_h[0], pa_l[0]);
            pack_pair(e0[2], e0[3], pa_h[1], pa_l[1]);
            pack_pair(e1[0], e1[1], pa_h[2], pa_l[2]);
            pack_pair(e1[2], e1[3], pa_h[3], pa_l[3]);
#pragma unroll
            for (int nt2 = 0; nt2 < 8; nt2++) {
                int k0 = ks2 * 16 + c2;
                uint32_t vbh[2], vbl[2];
                vbh[0] = *(const uint32_t*)&Vth[(nt2 * 8 + fr) * VSP + k0];
                vbh[1] = *(const uint32_t*)&Vth[(nt2 * 8 + fr) * VSP + k0 + 8];
                vbl[0] = *(const uint32_t*)&Vtl[(nt2 * 8 + fr) * VSP + k0];
                vbl[1] = *(const uint32_t*)&Vtl[(nt2 * 8 + fr) * VSP + k0 + 8];
                mma_bf16(oacc[nt2], pa_h, vbh);
                mma_bf16(oacc[nt2], pa_h, vbl);
                mma_bf16(oacc[nt2], pa_l, vbh);
            }
        }
    }

    // ---- finalize: scene term, divide, write bf16 hi/lo ----
    // reduce den across the 4 lanes sharing a row
    den0 += __shfl_xor_sync(0xffffffffu, den0, 1);
    den0 += __shfl_xor_sync(0xffffffffu, den0, 2);
    den1 += __shfl_xor_sync(0xffffffffu, den1, 1);
    den1 += __shfl_xor_sync(0xffffffffu, den1, 2);

    const int r0g = q0 + wq + fr;
    const float* w0v = w0g + (b * HEADS + h) * SEQ;
    float wA = w0v[r0g], wB = w0v[r0g + 8];
    float invA = 1.0f / (den0 + wA);
    float invB = 1.0f / (den1 + wB);
    const float* vsc = vs_scene + b * FDIM + h * HD;

#pragma unroll
    for (int nt2 = 0; nt2 < 8; nt2++) {
        int d0 = nt2 * 8 + c2;
        float2 vs2 = *(const float2*)(vsc + d0);
        float ax = (oacc[nt2][0] + wA * vs2.x) * invA;
        float ay = (oacc[nt2][1] + wA * vs2.y) * invA;
        float bx = (oacc[nt2][2] + wB * vs2.x) * invB;
        float by = (oacc[nt2][3] + wB * vs2.y) * invB;
        uint32_t h0, l0, h1, l1;
        pack_pair(ax, ay, h0, l0);
        pack_pair(bx, by, h1, l1);
        size_t baseA = (size_t)(b * SEQ + r0g) * FDIM + h * HD + d0;
        size_t baseB = (size_t)(b * SEQ + r0g + 8) * FDIM + h * HD + d0;
        *(uint32_t*)&ahi[baseA] = h0;
        *(uint32_t*)&alo[baseA] = l0;
        *(uint32_t*)&ahi[baseB] = h1;
        *(uint32_t*)&alo[baseB] = l1;
    }
}

// ===========================================================================
// Launch
// ===========================================================================
extern "C" void kernel_launch(void* const* d_in, const int* in_sizes, int n_in,
                              void* d_out, int out_size)
{
    (void)in_sizes; (void)n_in; (void)out_size;
    const float* feature = (const float*)d_in[0];
    const float* scene   = (const float*)d_in[1];
    const float* rel     = (const float*)d_in[2];
    const float* Wq = (const float*)d_in[3];  const float* bq = (const float*)d_in[4];
    const float* Wk = (const float*)d_in[5];  const float* bk = (const float*)d_in[6];
    const float* Wv = (const float*)d_in[7];  const float* bv = (const float*)d_in[8];
    const float* Wo = (const float*)d_in[9];  const float* bo = (const float*)d_in[10];
    float* out = (float*)d_out;

    float *qf, *qs, *ks, *vs, *R1, *w0;
    cudaGetSymbolAddress((void**)&qf, g_qf);
    cudaGetSymbolAddress((void**)&qs, g_qs);
    cudaGetSymbolAddress((void**)&ks, g_ks);
    cudaGetSymbolAddress((void**)&vs, g_vs);
    cudaGetSymbolAddress((void**)&R1, g_R1);
    cudaGetSymbolAddress((void**)&w0, g_w0);

    __nv_bfloat16 *fhi, *flo, *wqh, *wql, *wkh, *wkl, *wvh, *wvl, *woh, *wol;
    __nv_bfloat16 *qhi, *qlo, *khi, *klo, *vhi, *vlo, *ahi, *alo;
    cudaGetSymbolAddress((void**)&fhi, g_fhi);
    cudaGetSymbolAddress((void**)&flo, g_flo);
    cudaGetSymbolAddress((void**)&wqh, g_wqh);
    cudaGetSymbolAddress((void**)&wql, g_wql);
    cudaGetSymbolAddress((void**)&wkh, g_wkh);
    cudaGetSymbolAddress((void**)&wkl, g_wkl);
    cudaGetSymbolAddress((void**)&wvh, g_wvh);
    cudaGetSymbolAddress((void**)&wvl, g_wvl);
    cudaGetSymbolAddress((void**)&woh, g_woh);
    cudaGetSymbolAddress((void**)&wol, g_wol);
    cudaGetSymbolAddress((void**)&qhi, g_qhi);
    cudaGetSymbolAddress((void**)&qlo, g_qlo);
    cudaGetSymbolAddress((void**)&khi, g_khi);
    cudaGetSymbolAddress((void**)&klo, g_klo);
    cudaGetSymbolAddress((void**)&vhi, g_vhi);
    cudaGetSymbolAddress((void**)&vlo, g_vlo);
    cudaGetSymbolAddress((void**)&ahi, g_ahi);
    cudaGetSymbolAddress((void**)&alo, g_alo);

    cudaFuncSetAttribute(gemm_mma,
                         cudaFuncAttributeMaxDynamicSharedMemorySize, GSM_TOT);
    cudaFuncSetAttribute(attn_mma,
                         cudaFuncAttributeMaxDynamicSharedMemorySize, ASM_TOT);

    const int NF = BATCH * NTOK * FDIM;
    const int NW = FDIM * FDIM;

    // Splits
    split_kernel<<<NF / 1024, 256>>>(feature, fhi, flo, NF);
    split_kernel<<<NW / 1024, 256>>>(Wq, wqh, wql, NW);
    split_kernel<<<NW / 1024, 256>>>(Wk, wkh, wkl, NW);
    split_kernel<<<NW / 1024, 256>>>(Wv, wvh, wvl, NW);
    split_kernel<<<NW / 1024, 256>>>(Wo, woh, wol, NW);

    // Scene QKV + R1
    scene_qkv_kernel<<<1536, 256>>>(scene, Wq, bq, Wk, bk, Wv, bv, qs, ks, vs);
    r1_kernel<<<256, 256>>>(rel, R1);

    // Feature QKV (bf16 hi/lo epilogues; Q also fp32 for w0)
    dim3 gq(FDIM / 128, (BATCH * NTOK) / 128);   // (8, 32)
    gemm_mma<<<gq, 256, GSM_TOT>>>(fhi, flo, wqh, wql, bq, qf,   qhi, qlo, FDIM);
    gemm_mma<<<gq, 256, GSM_TOT>>>(fhi, flo, wkh, wkl, bk, NULL, khi, klo, FDIM);
    gemm_mma<<<gq, 256, GSM_TOT>>>(fhi, flo, wvh, wvl, bv, NULL, vhi, vlo, FDIM);

    // Scene-key closed form weights
    w0_kernel<<<(BATCH * HEADS * SEQ) / 8, 256>>>(qf, qs, ks, R1, w0);

    // Attention (tensor-core)
    dim3 ga(SEQ / BQ, HEADS, BATCH);   // (16, 16, 4)
    attn_mma<<<ga, 256, ASM_TOT>>>(qhi, qlo, khi, klo, vhi, vlo,
                                   qs, vs, rel, w0, ahi, alo);

    // Output projection -> d_out (fp32)
    dim3 go(FDIM / 128, (BATCH * SEQ) / 128);    // (8, 64)
    gemm_mma<<<go, 256, GSM_TOT>>>(ahi, alo, woh, wol, bo, out, NULL, NULL, FDIM);
}